// round 10
// baseline (speedup 1.0000x reference)
#include <cuda_runtime.h>

// MSFNO1d: B=32, L=4096, H=64, NL=4, modes {512,1024,2048}
#define BB 32
#define HH 64
#define LL 4096
#define NF 2048

typedef unsigned long long ull;

// ---- scratch (SoA planes for spectral data) ----
__device__ float  g_v[BB*HH*LL];
__device__ float  g_s[BB*HH*LL];
__device__ float  g_Xr[HH*BB*NF];         // Re rfft(v)  [i][b][f]
__device__ float  g_Xi[HH*BB*NF];         // Im
__device__ float  g_Yr[HH*BB*NF];         // Re mixed    [o][b][f]
__device__ float  g_Yi[HH*BB*NF];         // Im
__device__ float2 g_twF[2048];            // e^{-2pi i k/2048}
__device__ float2 g_tw4096[2048];         // e^{-2pi i k/4096}

// ---- helpers ----
__device__ __forceinline__ float2 cmul(float2 a, float2 b){
    return make_float2(a.x*b.x - a.y*b.y, a.x*b.y + a.y*b.x);
}
__device__ __forceinline__ float2 cadd(float2 a, float2 b){ return make_float2(a.x+b.x, a.y+b.y); }
__device__ __forceinline__ float2 csub(float2 a, float2 b){ return make_float2(a.x-b.x, a.y-b.y); }
__device__ __forceinline__ ull pack2(float lo, float hi){
    ull r; asm("mov.b64 %0,{%1,%2};" : "=l"(r) : "f"(lo), "f"(hi)); return r;
}
__device__ __forceinline__ float2 unpack2(ull v){
    float2 r; asm("mov.b64 {%0,%1},%2;" : "=f"(r.x), "=f"(r.y) : "l"(v)); return r;
}
__device__ __forceinline__ void fma2(ull &acc, ull a, ull b){
    asm("fma.rn.f32x2 %0,%1,%2,%0;" : "+l"(acc) : "l"(a), "l"(b));
}
__device__ __forceinline__ float tanh_fast(float x){
    float y; asm("tanh.approx.f32 %0,%1;" : "=f"(y) : "f"(x)); return y;
}
__device__ __forceinline__ float gelu_tanh(float x){
    float x3 = x*x*x;
    return 0.5f*x*(1.0f + tanh_fast(0.7978845608028654f*(x + 0.044715f*x3)));
}
__device__ __forceinline__ void cpasync16(unsigned dst, const void* src){
    asm volatile("cp.async.cg.shared.global [%0], [%1], 16;" :: "r"(dst), "l"(src));
}
#define CP_COMMIT() asm volatile("cp.async.commit_group;")

// ---- twiddle init ----
__global__ void init_tw_kernel(){
    int k = blockIdx.x*256 + threadIdx.x;
    if (k < 2048){
        double s, c; sincospi(-2.0*(double)k/2048.0, &s, &c);
        g_twF[k] = make_float2((float)c, (float)s);
        double s2, c2; sincospi(-2.0*(double)k/4096.0, &s2, &c2);
        g_tw4096[k] = make_float2((float)c2, (float)s2);
    }
}

// ---- encoder ----
__global__ void encoder_kernel(const float* __restrict__ u, const float* __restrict__ x,
                               const float* __restrict__ ew, const float* __restrict__ eb){
    int b = blockIdx.y;
    int t = blockIdx.x*256 + threadIdx.x;
    float xv = x[(size_t)b*LL + t];
    float u0 = u[((size_t)b*3 + 0)*LL + t];
    float u1 = u[((size_t)b*3 + 1)*LL + t];
    float u2 = u[((size_t)b*3 + 2)*LL + t];
    #pragma unroll 4
    for (int h = 0; h < HH; h++){
        float r = eb[h] + ew[h*4+0]*xv + ew[h*4+1]*u0 + ew[h*4+2]*u1 + ew[h*4+3]*u2;
        g_v[((size_t)b*HH + h)*LL + t] = r;
    }
}

// ===================== Stockham radix-8 FFT (N=2048, 256 threads) =====================
template<int MODE> __device__ __forceinline__ int swz(int a){
    if (MODE==1) return a ^ (((a>>3) ^ (a>>6)) & 7);     // gen A
    if (MODE==2) return a ^ (((a>>6) & 7) << 3);         // gen B
    return a;                                            // identity
}

__device__ __forceinline__ void radix8(const float2* x, float2* c){
    const float r = 0.70710678118654752f;
    float2 y0 = cadd(x[0],x[4]), y4 = csub(x[0],x[4]);
    float2 y1 = cadd(x[1],x[5]), t5 = csub(x[1],x[5]);
    float2 y2 = cadd(x[2],x[6]), t6 = csub(x[2],x[6]);
    float2 y3 = cadd(x[3],x[7]), t7 = csub(x[3],x[7]);
    float2 y5 = make_float2(r*(t5.x+t5.y), r*(t5.y-t5.x));
    float2 y6 = make_float2(t6.y, -t6.x);
    float2 y7 = make_float2(r*(t7.y-t7.x), -r*(t7.x+t7.y));
    float2 z0 = cadd(y0,y2), z2 = csub(y0,y2);
    float2 z1 = cadd(y1,y3), t3 = csub(y1,y3);
    float2 z3 = make_float2(t3.y, -t3.x);
    float2 z4 = cadd(y4,y6), z6 = csub(y4,y6);
    float2 z5 = cadd(y5,y7), u7 = csub(y5,y7);
    float2 z7 = make_float2(u7.y, -u7.x);
    c[0] = cadd(z0,z1); c[4] = csub(z0,z1);
    c[2] = cadd(z2,z3); c[6] = csub(z2,z3);
    c[1] = cadd(z4,z5); c[5] = csub(z4,z5);
    c[3] = cadd(z6,z7); c[7] = csub(z6,z7);
}

// log-depth twiddle application: c[k] *= w1^k
__device__ __forceinline__ void twchain(float2* c, float2 w1){
    float2 w2 = cmul(w1, w1);
    float2 w3 = cmul(w2, w1);
    float2 w4 = cmul(w2, w2);
    float2 w5 = cmul(w2, w3);
    float2 w6 = cmul(w3, w3);
    float2 w7 = cmul(w3, w4);
    c[1] = cmul(c[1], w1);
    c[2] = cmul(c[2], w2);
    c[3] = cmul(c[3], w3);
    c[4] = cmul(c[4], w4);
    c[5] = cmul(c[5], w5);
    c[6] = cmul(c[6], w6);
    c[7] = cmul(c[7], w7);
}

template<int LOGS, int TSTR, int SWIN, int SWOUT>
__device__ __forceinline__ void stage8s(const float* ri, const float* im,
                                        float* ro, float* io, int tid){
    int q = tid & ((1<<LOGS)-1);
    int p = tid >> LOGS;
    int base = q + (p << LOGS);
    float2 a[8], c[8];
    #pragma unroll
    for (int j = 0; j < 8; j++){
        int s = swz<SWIN>(base + 256*j);
        a[j] = make_float2(ri[s], im[s]);
    }
    radix8(a, c);
    twchain(c, g_twF[p*TSTR]);
    #pragma unroll
    for (int k = 0; k < 8; k++){
        int s = swz<SWOUT>(q + ((8*p + k) << LOGS));
        ro[s] = c[k].x; io[s] = c[k].y;
    }
}

__device__ __forceinline__ void stage8g(const float2* __restrict__ src,
                                        float* ro, float* io, int tid){
    float2 a[8], c[8];
    #pragma unroll
    for (int j = 0; j < 8; j++) a[j] = src[tid + 256*j];
    radix8(a, c);
    twchain(c, g_twF[tid]);
    #pragma unroll
    for (int k = 0; k < 8; k++){
        int s = swz<1>(8*tid + k);
        ro[s] = c[k].x; io[s] = c[k].y;
    }
}

__device__ __forceinline__ void stage4s(const float* ri, const float* im,
                                        float* ro, float* io, int tid){
    #pragma unroll
    for (int h = 0; h < 2; h++){
        int q = tid + 256*h;
        float2 x0 = make_float2(ri[q],      im[q]);
        float2 x1 = make_float2(ri[q+512],  im[q+512]);
        float2 x2 = make_float2(ri[q+1024], im[q+1024]);
        float2 x3 = make_float2(ri[q+1536], im[q+1536]);
        float2 y0 = cadd(x0,x2), y2 = csub(x0,x2);
        float2 y1 = cadd(x1,x3), t3 = csub(x1,x3);
        float2 y3 = make_float2(t3.y, -t3.x);
        float2 c0 = cadd(y0,y1), c2 = csub(y0,y1);
        float2 c1 = cadd(y2,y3), c3 = csub(y2,y3);
        ro[q]      = c0.x; io[q]      = c0.y;
        ro[q+512]  = c1.x; io[q+512]  = c1.y;
        ro[q+1024] = c2.x; io[q+1024] = c2.y;
        ro[q+1536] = c3.x; io[q+1536] = c3.y;
    }
}

// ---- forward rfft: v row (4096 real) -> SoA planes g_Xr/g_Xi ----
__global__ __launch_bounds__(256) void fft_fwd_kernel(){
    __shared__ float r0[2048], i0[2048], r1[2048], i1[2048];
    int b = blockIdx.x, ch = blockIdx.y;
    int tid = threadIdx.x;
    const float2* src = (const float2*)(g_v + ((size_t)b*HH + ch)*LL);
    stage8g(src, r0, i0, tid);
    __syncthreads();
    stage8s<3,8,1,2>(r0, i0, r1, i1, tid);
    __syncthreads();
    stage8s<6,64,2,0>(r1, i1, r0, i0, tid);
    __syncthreads();
    stage4s(r0, i0, r1, i1, tid);
    __syncthreads();
    float* dR = g_Xr + ((size_t)ch*BB + b)*NF;
    float* dI = g_Xi + ((size_t)ch*BB + b)*NF;
    for (int k = tid; k < 2048; k += 256){
        float2 Zk = make_float2(r1[k], i1[k]);
        int kn = (2048 - k) & 2047;
        float2 Zn = make_float2(r1[kn], i1[kn]);
        float2 Fe = make_float2(0.5f*(Zk.x + Zn.x),  0.5f*(Zk.y - Zn.y));
        float2 Fo = make_float2(0.5f*(Zk.y + Zn.y), -0.5f*(Zk.x - Zn.x));
        float2 t  = cmul(g_tw4096[k], Fo);
        dR[k] = Fe.x + t.x;
        dI[k] = Fe.y + t.y;
    }
}

// ---- inverse rfft from SoA planes g_Yr/g_Yi + bias -> g_s ----
__global__ __launch_bounds__(256) void fft_inv_kernel(const float* __restrict__ sb0,
                                                      const float* __restrict__ sb1,
                                                      const float* __restrict__ sb2, int l){
    __shared__ float r0[2048], i0[2048], r1[2048], i1[2048];
    int b = blockIdx.x, o = blockIdx.y;
    int tid = threadIdx.x;
    const float* sR = g_Yr + ((size_t)o*BB + b)*NF;
    const float* sI = g_Yi + ((size_t)o*BB + b)*NF;
    for (int k = tid; k < 2048; k += 256){
        float2 Xk = make_float2(sR[k], sI[k]);
        float2 Xn;
        if (k == 0){ Xk.y = 0.0f; Xn = make_float2(0.0f, 0.0f); }
        else        { Xn = make_float2(sR[2048 - k], sI[2048 - k]); }
        float2 Fe = make_float2(0.5f*(Xk.x + Xn.x), 0.5f*(Xk.y - Xn.y));
        float2 D  = make_float2(0.5f*(Xk.x - Xn.x), 0.5f*(Xk.y + Xn.y));
        float2 w  = g_tw4096[k];
        float2 Fo = make_float2(D.x*w.x + D.y*w.y, D.y*w.x - D.x*w.y);
        r0[k] =  Fe.x - Fo.y;
        i0[k] = -(Fe.y + Fo.x);
    }
    __syncthreads();
    stage8s<0,1,0,1>(r0, i0, r1, i1, tid);
    __syncthreads();
    stage8s<3,8,1,2>(r1, i1, r0, i0, tid);
    __syncthreads();
    stage8s<6,64,2,0>(r0, i0, r1, i1, tid);
    __syncthreads();
    stage4s(r1, i1, r0, i0, tid);
    __syncthreads();
    float bias = sb0[l*HH + o] + sb1[l*HH + o] + sb2[l*HH + o];
    float2* dst = (float2*)(g_s + ((size_t)b*HH + o)*LL);
    const float sc = 1.0f/2048.0f;
    for (int n = tid; n < 2048; n += 256){
        dst[n] = make_float2(r0[n]*sc + bias, -i0[n]*sc + bias);
    }
}

// ===================== spectral mixing v7: 4-stage cp.async pipeline, i=1 chunks ==========
// Y[o,b,f] = sum_i X[i,b,f]*Wsum[i,o,f] (complex). Lane f32x2 = freqs (f, f+1).
// block: 16b x 8o x 64f; 8 warps; thread 4b x 4o (32 ull accs). W streams consumed
// directly from staged AoS buffers (no sum pass); 3 cp.async groups always in flight.
// smem (floats): XsR[4][16][64] @0 (16KB) | XsI @4096 | W2s f2[4][8][64] @8192 (16KB)
//                W1s @12288 | W0s @16384 ; total 20480 floats = 80KB.
__global__ __launch_bounds__(256, 2) void spec_gemm_kernel(const float* __restrict__ w0,
                                                           const float* __restrict__ w1,
                                                           const float* __restrict__ w2, int l){
    extern __shared__ float sm[];
    float*  XsR = sm;
    float*  XsI = sm + 4096;
    float2* W2s = (float2*)(sm + 8192);
    float2* W1s = (float2*)(sm + 12288);
    float2* W0s = (float2*)(sm + 16384);
    unsigned sb = (unsigned)__cvta_generic_to_shared(sm);

    int o0 = blockIdx.x * 8;
    int f0 = blockIdx.y * 64;
    int bh = blockIdx.z * 16;
    int tid  = threadIdx.x;
    int lane = tid & 31;
    int g    = tid >> 5;          // 8 warps
    int b0   = (g & 3) * 4;
    int oo   = (g >> 2) * 4;
    bool p1 = (f0 < 1024), p0 = (f0 < 512);
    const float2* W2p = (const float2*)w2 + (size_t)l*HH*HH*2048;
    const float2* W1p = (const float2*)w1 + (size_t)l*HH*HH*1024;
    const float2* W0p = (const float2*)w0 + (size_t)l*HH*HH*512;

    // staging coords
    int sx_pl = tid >> 7;                       // X plane (0=Re,1=Im), 2 copies/thread
    int sx_bb = (tid >> 4) & 7;                 // with r-loop covers 16 b
    int sx_f  = (tid & 15) * 4;
    int sw_o  = tid >> 5;                       // 8 rows
    int sw_q  = (tid & 31) * 2;                 // float2 units

    ull accR[4][4], accI[4][4];
    #pragma unroll
    for (int bi = 0; bi < 4; bi++)
        #pragma unroll
        for (int oi = 0; oi < 4; oi++){ accR[bi][oi] = 0ull; accI[bi][oi] = 0ull; }

    // stage one i into buffer bufs: X 8KB (512x16B), W 4KB/stream (256x16B)
    #define STAGE(ci, bufs) do{                                                        \
        _Pragma("unroll")                                                              \
        for (int r = 0; r < 2; r++){                                                   \
            int bb = sx_bb + r*8;                                                      \
            size_t xofs = ((size_t)(ci)*BB + bh + bb)*NF + f0 + sx_f;                  \
            unsigned xslot = (((bufs)*16 + bb)*64 + sx_f)*4u + (unsigned)sx_pl*16384u; \
            cpasync16(sb + xslot, (sx_pl ? g_Xi : g_Xr) + xofs);                       \
        }                                                                              \
        size_t wb = ((size_t)(ci)*HH + o0 + sw_o);                                     \
        unsigned wslot = (((bufs)*8 + sw_o)*64 + sw_q)*8u;                             \
        cpasync16(sb + 32768u + wslot, W2p + wb*2048 + f0 + sw_q);                     \
        if (p1) cpasync16(sb + 49152u + wslot, W1p + wb*1024 + f0 + sw_q);             \
        if (p0) cpasync16(sb + 65536u + wslot, W0p + wb*512  + f0 + sw_q);             \
    } while(0)

    STAGE(0, 0); CP_COMMIT();
    STAGE(1, 1); CP_COMMIT();
    STAGE(2, 2); CP_COMMIT();

    for (int c = 0; c < 64; c++){
        int buf = c & 3;
        if (c < 62)      asm volatile("cp.async.wait_group 2;");
        else if (c == 62) asm volatile("cp.async.wait_group 1;");
        else              asm volatile("cp.async.wait_group 0;");
        __syncthreads();
        if (c < 61){ STAGE(c+3, (c+3)&3); CP_COMMIT(); }

        // build summed W (SoA f32x2) in registers for this thread's 4 o's
        ull wr[4], wi[4];
        #pragma unroll
        for (int oi = 0; oi < 4; oi++){
            int ws = ((buf*8) + oo + oi)*64 + 2*lane;   // float2 index, 16B aligned
            float4 w = *(const float4*)&W2s[ws];
            if (p1){ float4 a = *(const float4*)&W1s[ws];
                     w.x += a.x; w.y += a.y; w.z += a.z; w.w += a.w; }
            if (p0){ float4 a = *(const float4*)&W0s[ws];
                     w.x += a.x; w.y += a.y; w.z += a.z; w.w += a.w; }
            wr[oi] = pack2(w.x, w.z);
            wi[oi] = pack2(w.y, w.w);
        }
        // consume: 4b x 4o
        #pragma unroll
        for (int bi = 0; bi < 4; bi++){
            int xs = (buf*16 + b0 + bi)*64 + 2*lane;
            ull xr  = *(const ull*)&XsR[xs];
            ull xi  = *(const ull*)&XsI[xs];
            ull xin = xi ^ 0x8000000080000000ULL;
            #pragma unroll
            for (int oi = 0; oi < 4; oi++){
                fma2(accR[bi][oi], xr,  wr[oi]);
                fma2(accR[bi][oi], xin, wi[oi]);
                fma2(accI[bi][oi], xr,  wi[oi]);
                fma2(accI[bi][oi], xi,  wr[oi]);
            }
        }
    }
    #undef STAGE

    #pragma unroll
    for (int bi = 0; bi < 4; bi++)
        #pragma unroll
        for (int oi = 0; oi < 4; oi++){
            size_t ofs = ((size_t)(o0 + oo + oi)*BB + bh + b0 + bi)*NF + f0 + 2*lane;
            *(ull*)&g_Yr[ofs] = accR[bi][oi];
            *(ull*)&g_Yi[ofs] = accI[bi][oi];
        }
}

// ---- pointwise: v += conv2(gelu(conv1(s))); register-tiled 4o x 8t ----
__global__ __launch_bounds__(256) void pointwise_kernel(const float* __restrict__ w1,
                                                        const float* __restrict__ b1,
                                                        const float* __restrict__ w2,
                                                        const float* __restrict__ b2, int l){
    int b  = blockIdx.y;
    int t0 = blockIdx.x * 128;
    __shared__ float ss[64][128];
    __shared__ float Wb[64][64];
    int tid = threadIdx.x;
    int ts  = tid & 15;
    int og  = tid >> 4;

    #pragma unroll
    for (int r = 0; r < 16; r++){
        int idx = tid + 256*r;
        int i = idx >> 6, c2 = idx & 63;
        *(float2*)&ss[i][c2*2] = *(const float2*)&g_s[((size_t)b*HH + i)*LL + t0 + c2*2];
    }
    #pragma unroll
    for (int r = 0; r < 16; r++){
        int idx = tid + 256*r;
        Wb[idx >> 6][idx & 63] = w1[(size_t)l*4096 + idx];
    }
    __syncthreads();

    ull acc[4][4];
    #pragma unroll
    for (int oi = 0; oi < 4; oi++){
        float bv = b1[l*HH + og*4 + oi];
        #pragma unroll
        for (int j = 0; j < 4; j++) acc[oi][j] = pack2(bv, bv);
    }
    for (int i = 0; i < 64; i++){
        ull sv[4];
        #pragma unroll
        for (int j = 0; j < 4; j++) sv[j] = *(const ull*)&ss[i][2*ts + 32*j];
        #pragma unroll
        for (int oi = 0; oi < 4; oi++){
            float w = Wb[og*4 + oi][i];
            ull wp = pack2(w, w);
            #pragma unroll
            for (int j = 0; j < 4; j++) fma2(acc[oi][j], wp, sv[j]);
        }
    }
    __syncthreads();
    #pragma unroll
    for (int oi = 0; oi < 4; oi++)
        #pragma unroll
        for (int j = 0; j < 4; j++){
            float2 a = unpack2(acc[oi][j]);
            ss[og*4 + oi][2*ts + 32*j]     = gelu_tanh(a.x);
            ss[og*4 + oi][2*ts + 32*j + 1] = gelu_tanh(a.y);
        }
    #pragma unroll
    for (int r = 0; r < 16; r++){
        int idx = tid + 256*r;
        Wb[idx >> 6][idx & 63] = w2[(size_t)l*4096 + idx];
    }
    __syncthreads();

    ull acc2[4][4];
    #pragma unroll
    for (int ci = 0; ci < 4; ci++){
        float bv = b2[l*HH + og*4 + ci];
        #pragma unroll
        for (int j = 0; j < 4; j++) acc2[ci][j] = pack2(bv, bv);
    }
    for (int o = 0; o < 64; o++){
        ull hv[4];
        #pragma unroll
        for (int j = 0; j < 4; j++) hv[j] = *(const ull*)&ss[o][2*ts + 32*j];
        #pragma unroll
        for (int ci = 0; ci < 4; ci++){
            float w = Wb[og*4 + ci][o];
            ull wp = pack2(w, w);
            #pragma unroll
            for (int j = 0; j < 4; j++) fma2(acc2[ci][j], wp, hv[j]);
        }
    }
    #pragma unroll
    for (int ci = 0; ci < 4; ci++){
        int c = og*4 + ci;
        #pragma unroll
        for (int j = 0; j < 4; j++){
            float2 a = unpack2(acc2[ci][j]);
            float2* vp = (float2*)(g_v + ((size_t)b*HH + c)*LL + t0 + 2*ts + 32*j);
            float2 vv = *vp;
            vv.x += a.x; vv.y += a.y;
            *vp = vv;
        }
    }
}

// ---- decoder ----
__global__ void decoder_kernel(const float* __restrict__ dw, const float* __restrict__ db,
                               float* __restrict__ out){
    int b = blockIdx.y;
    int t = blockIdx.x*256 + threadIdx.x;
    float acc = db[0];
    #pragma unroll 8
    for (int h = 0; h < HH; h++)
        acc += dw[h] * g_v[((size_t)b*HH + h)*LL + t];
    out[(size_t)b*LL + t] = acc;
}

extern "C" void kernel_launch(void* const* d_in, const int* in_sizes, int n_in,
                              void* d_out, int out_size){
    const float* u     = (const float*)d_in[0];
    const float* x     = (const float*)d_in[1];
    const float* enc_w = (const float*)d_in[2];
    const float* enc_b = (const float*)d_in[3];
    const float* dec_w = (const float*)d_in[4];
    const float* dec_b = (const float*)d_in[5];
    const float* c1w   = (const float*)d_in[6];
    const float* c1b   = (const float*)d_in[7];
    const float* c2w   = (const float*)d_in[8];
    const float* c2b   = (const float*)d_in[9];
    const float* sw0   = (const float*)d_in[10];
    const float* sb0   = (const float*)d_in[11];
    const float* sw1   = (const float*)d_in[12];
    const float* sb1   = (const float*)d_in[13];
    const float* sw2   = (const float*)d_in[14];
    const float* sb2   = (const float*)d_in[15];
    float* out = (float*)d_out;

    const int SMEM_SPEC = 20480 * 4;   // 80KB dynamic
    cudaFuncSetAttribute(spec_gemm_kernel,
                         cudaFuncAttributeMaxDynamicSharedMemorySize, SMEM_SPEC);

    init_tw_kernel<<<8, 256>>>();
    encoder_kernel<<<dim3(LL/256, BB), 256>>>(u, x, enc_w, enc_b);
    for (int l = 0; l < 4; l++){
        fft_fwd_kernel<<<dim3(BB, HH), 256>>>();
        spec_gemm_kernel<<<dim3(HH/8, NF/64, 2), 256, SMEM_SPEC>>>(sw0, sw1, sw2, l);
        fft_inv_kernel<<<dim3(BB, HH), 256>>>(sb0, sb1, sb2, l);
        pointwise_kernel<<<dim3(LL/128, BB), 256>>>(c1w, c1b, c2w, c2b, l);
    }
    decoder_kernel<<<dim3(LL/256, BB), 256>>>(dec_w, dec_b, out);
}

// round 11
// speedup vs baseline: 1.1239x; 1.1239x over previous
#include <cuda_runtime.h>

// MSFNO1d: B=32, L=4096, H=64, NL=4, modes {512,1024,2048}
#define BB 32
#define HH 64
#define LL 4096
#define NF 2048

typedef unsigned long long ull;

// ---- scratch ----
__device__ float  g_v[BB*HH*LL];
__device__ float  g_s[BB*HH*LL];
__device__ float4 g_X4[HH*BB*1024];       // rfft(v)  [i][b][quad m]: (R2m,R2m+1,I2m,I2m+1)
__device__ float4 g_Y4[HH*BB*1024];       // mixed    [o][b][quad]
__device__ float2 g_twF[2048];            // e^{-2pi i k/2048}
__device__ float2 g_tw4096[2048];         // e^{-2pi i k/4096}

// ---- helpers ----
__device__ __forceinline__ float2 cmul(float2 a, float2 b){
    return make_float2(a.x*b.x - a.y*b.y, a.x*b.y + a.y*b.x);
}
__device__ __forceinline__ float2 cadd(float2 a, float2 b){ return make_float2(a.x+b.x, a.y+b.y); }
__device__ __forceinline__ float2 csub(float2 a, float2 b){ return make_float2(a.x-b.x, a.y-b.y); }
__device__ __forceinline__ ull pack2(float lo, float hi){
    ull r; asm("mov.b64 %0,{%1,%2};" : "=l"(r) : "f"(lo), "f"(hi)); return r;
}
__device__ __forceinline__ float2 unpack2(ull v){
    float2 r; asm("mov.b64 {%0,%1},%2;" : "=f"(r.x), "=f"(r.y) : "l"(v)); return r;
}
__device__ __forceinline__ void fma2(ull &acc, ull a, ull b){
    asm("fma.rn.f32x2 %0,%1,%2,%0;" : "+l"(acc) : "l"(a), "l"(b));
}
__device__ __forceinline__ float tanh_fast(float x){
    float y; asm("tanh.approx.f32 %0,%1;" : "=f"(y) : "f"(x)); return y;
}
__device__ __forceinline__ float gelu_tanh(float x){
    float x3 = x*x*x;
    return 0.5f*x*(1.0f + tanh_fast(0.7978845608028654f*(x + 0.044715f*x3)));
}
__device__ __forceinline__ void cpasync16(unsigned dst, const void* src){
    asm volatile("cp.async.cg.shared.global [%0], [%1], 16;" :: "r"(dst), "l"(src));
}
#define CP_COMMIT() asm volatile("cp.async.commit_group;")
#define CP_WAIT0()  asm volatile("cp.async.wait_group 0;")

// ---- twiddle init ----
__global__ void init_tw_kernel(){
    int k = blockIdx.x*256 + threadIdx.x;
    if (k < 2048){
        double s, c; sincospi(-2.0*(double)k/2048.0, &s, &c);
        g_twF[k] = make_float2((float)c, (float)s);
        double s2, c2; sincospi(-2.0*(double)k/4096.0, &s2, &c2);
        g_tw4096[k] = make_float2((float)c2, (float)s2);
    }
}

// ---- encoder ----
__global__ void encoder_kernel(const float* __restrict__ u, const float* __restrict__ x,
                               const float* __restrict__ ew, const float* __restrict__ eb){
    int b = blockIdx.y;
    int t = blockIdx.x*256 + threadIdx.x;
    float xv = x[(size_t)b*LL + t];
    float u0 = u[((size_t)b*3 + 0)*LL + t];
    float u1 = u[((size_t)b*3 + 1)*LL + t];
    float u2 = u[((size_t)b*3 + 2)*LL + t];
    #pragma unroll 4
    for (int h = 0; h < HH; h++){
        float r = eb[h] + ew[h*4+0]*xv + ew[h*4+1]*u0 + ew[h*4+2]*u1 + ew[h*4+3]*u2;
        g_v[((size_t)b*HH + h)*LL + t] = r;
    }
}

// ===================== Stockham radix-8 FFT (N=2048, 256 threads) =====================
template<int MODE> __device__ __forceinline__ int swz(int a){
    if (MODE==1) return a ^ (((a>>3) ^ (a>>6)) & 7);     // gen A
    if (MODE==2) return a ^ (((a>>6) & 7) << 3);         // gen B
    return a;                                            // identity
}

__device__ __forceinline__ void radix8(const float2* x, float2* c){
    const float r = 0.70710678118654752f;
    float2 y0 = cadd(x[0],x[4]), y4 = csub(x[0],x[4]);
    float2 y1 = cadd(x[1],x[5]), t5 = csub(x[1],x[5]);
    float2 y2 = cadd(x[2],x[6]), t6 = csub(x[2],x[6]);
    float2 y3 = cadd(x[3],x[7]), t7 = csub(x[3],x[7]);
    float2 y5 = make_float2(r*(t5.x+t5.y), r*(t5.y-t5.x));
    float2 y6 = make_float2(t6.y, -t6.x);
    float2 y7 = make_float2(r*(t7.y-t7.x), -r*(t7.x+t7.y));
    float2 z0 = cadd(y0,y2), z2 = csub(y0,y2);
    float2 z1 = cadd(y1,y3), t3 = csub(y1,y3);
    float2 z3 = make_float2(t3.y, -t3.x);
    float2 z4 = cadd(y4,y6), z6 = csub(y4,y6);
    float2 z5 = cadd(y5,y7), u7 = csub(y5,y7);
    float2 z7 = make_float2(u7.y, -u7.x);
    c[0] = cadd(z0,z1); c[4] = csub(z0,z1);
    c[2] = cadd(z2,z3); c[6] = csub(z2,z3);
    c[1] = cadd(z4,z5); c[5] = csub(z4,z5);
    c[3] = cadd(z6,z7); c[7] = csub(z6,z7);
}

// log-depth twiddle application: c[k] *= w1^k
__device__ __forceinline__ void twchain(float2* c, float2 w1){
    float2 w2 = cmul(w1, w1);
    float2 w3 = cmul(w2, w1);
    float2 w4 = cmul(w2, w2);
    float2 w5 = cmul(w2, w3);
    float2 w6 = cmul(w3, w3);
    float2 w7 = cmul(w3, w4);
    c[1] = cmul(c[1], w1);
    c[2] = cmul(c[2], w2);
    c[3] = cmul(c[3], w3);
    c[4] = cmul(c[4], w4);
    c[5] = cmul(c[5], w5);
    c[6] = cmul(c[6], w6);
    c[7] = cmul(c[7], w7);
}

template<int LOGS, int TSTR, int SWIN, int SWOUT>
__device__ __forceinline__ void stage8s(const float* ri, const float* im,
                                        float* ro, float* io, int tid){
    int q = tid & ((1<<LOGS)-1);
    int p = tid >> LOGS;
    int base = q + (p << LOGS);
    float2 a[8], c[8];
    #pragma unroll
    for (int j = 0; j < 8; j++){
        int s = swz<SWIN>(base + 256*j);
        a[j] = make_float2(ri[s], im[s]);
    }
    radix8(a, c);
    twchain(c, g_twF[p*TSTR]);
    #pragma unroll
    for (int k = 0; k < 8; k++){
        int s = swz<SWOUT>(q + ((8*p + k) << LOGS));
        ro[s] = c[k].x; io[s] = c[k].y;
    }
}

__device__ __forceinline__ void stage8g(const float2* __restrict__ src,
                                        float* ro, float* io, int tid){
    float2 a[8], c[8];
    #pragma unroll
    for (int j = 0; j < 8; j++) a[j] = src[tid + 256*j];
    radix8(a, c);
    twchain(c, g_twF[tid]);
    #pragma unroll
    for (int k = 0; k < 8; k++){
        int s = swz<1>(8*tid + k);
        ro[s] = c[k].x; io[s] = c[k].y;
    }
}

__device__ __forceinline__ void stage4s(const float* ri, const float* im,
                                        float* ro, float* io, int tid){
    #pragma unroll
    for (int h = 0; h < 2; h++){
        int q = tid + 256*h;
        float2 x0 = make_float2(ri[q],      im[q]);
        float2 x1 = make_float2(ri[q+512],  im[q+512]);
        float2 x2 = make_float2(ri[q+1024], im[q+1024]);
        float2 x3 = make_float2(ri[q+1536], im[q+1536]);
        float2 y0 = cadd(x0,x2), y2 = csub(x0,x2);
        float2 y1 = cadd(x1,x3), t3 = csub(x1,x3);
        float2 y3 = make_float2(t3.y, -t3.x);
        float2 c0 = cadd(y0,y1), c2 = csub(y0,y1);
        float2 c1 = cadd(y2,y3), c3 = csub(y2,y3);
        ro[q]      = c0.x; io[q]      = c0.y;
        ro[q+512]  = c1.x; io[q+512]  = c1.y;
        ro[q+1024] = c2.x; io[q+1024] = c2.y;
        ro[q+1536] = c3.x; io[q+1536] = c3.y;
    }
}

// ---- forward rfft: v row (4096 real) -> quad layout g_X4 ----
__global__ __launch_bounds__(256) void fft_fwd_kernel(){
    __shared__ float r0[2048], i0[2048], r1[2048], i1[2048];
    int b = blockIdx.x, ch = blockIdx.y;
    int tid = threadIdx.x;
    const float2* src = (const float2*)(g_v + ((size_t)b*HH + ch)*LL);
    stage8g(src, r0, i0, tid);
    __syncthreads();
    stage8s<3,8,1,2>(r0, i0, r1, i1, tid);
    __syncthreads();
    stage8s<6,64,2,0>(r1, i1, r0, i0, tid);
    __syncthreads();
    stage4s(r0, i0, r1, i1, tid);
    __syncthreads();
    float4* dst = g_X4 + ((size_t)ch*BB + b)*1024;
    for (int m = tid; m < 1024; m += 256){
        int k0 = 2*m, k1 = 2*m + 1;
        // F(k0)
        float2 Zk = make_float2(r1[k0], i1[k0]);
        int kn = (2048 - k0) & 2047;
        float2 Zn = make_float2(r1[kn], i1[kn]);
        float2 Fe = make_float2(0.5f*(Zk.x + Zn.x),  0.5f*(Zk.y - Zn.y));
        float2 Fo = make_float2(0.5f*(Zk.y + Zn.y), -0.5f*(Zk.x - Zn.x));
        float2 t  = cmul(g_tw4096[k0], Fo);
        float R0 = Fe.x + t.x, I0 = Fe.y + t.y;
        // F(k1)
        Zk = make_float2(r1[k1], i1[k1]);
        kn = 2048 - k1;
        Zn = make_float2(r1[kn], i1[kn]);
        Fe = make_float2(0.5f*(Zk.x + Zn.x),  0.5f*(Zk.y - Zn.y));
        Fo = make_float2(0.5f*(Zk.y + Zn.y), -0.5f*(Zk.x - Zn.x));
        t  = cmul(g_tw4096[k1], Fo);
        float R1 = Fe.x + t.x, I1 = Fe.y + t.y;
        dst[m] = make_float4(R0, R1, I0, I1);
    }
}

// ---- inverse rfft from quad layout g_Y4 + bias -> g_s ----
__global__ __launch_bounds__(256) void fft_inv_kernel(const float* __restrict__ sb0,
                                                      const float* __restrict__ sb1,
                                                      const float* __restrict__ sb2, int l){
    __shared__ float r0[2048], i0[2048], r1[2048], i1[2048];
    int b = blockIdx.x, o = blockIdx.y;
    int tid = threadIdx.x;
    const float4* srcq = g_Y4 + ((size_t)o*BB + b)*1024;
    for (int m = tid; m < 1024; m += 256){
        float4 q = srcq[m];
        r1[2*m] = q.x; r1[2*m+1] = q.y;
        i1[2*m] = q.z; i1[2*m+1] = q.w;
    }
    __syncthreads();
    for (int k = tid; k < 2048; k += 256){
        float2 Xk = make_float2(r1[k], i1[k]);
        float2 Xn;
        if (k == 0){ Xk.y = 0.0f; Xn = make_float2(0.0f, 0.0f); }
        else        { Xn = make_float2(r1[2048 - k], i1[2048 - k]); }
        float2 Fe = make_float2(0.5f*(Xk.x + Xn.x), 0.5f*(Xk.y - Xn.y));
        float2 D  = make_float2(0.5f*(Xk.x - Xn.x), 0.5f*(Xk.y + Xn.y));
        float2 w  = g_tw4096[k];
        float2 Fo = make_float2(D.x*w.x + D.y*w.y, D.y*w.x - D.x*w.y);
        r0[k] =  Fe.x - Fo.y;
        i0[k] = -(Fe.y + Fo.x);
    }
    __syncthreads();
    stage8s<0,1,0,1>(r0, i0, r1, i1, tid);
    __syncthreads();
    stage8s<3,8,1,2>(r1, i1, r0, i0, tid);
    __syncthreads();
    stage8s<6,64,2,0>(r0, i0, r1, i1, tid);
    __syncthreads();
    stage4s(r1, i1, r0, i0, tid);
    __syncthreads();
    float bias = sb0[l*HH + o] + sb1[l*HH + o] + sb2[l*HH + o];
    float2* dst = (float2*)(g_s + ((size_t)b*HH + o)*LL);
    const float sc = 1.0f/2048.0f;
    for (int n = tid; n < 2048; n += 256){
        dst[n] = make_float2(r0[n]*sc + bias, -i0[n]*sc + bias);
    }
}

// ===================== spectral mixing v8: R9 pipeline + float4 quad loads ==========
// Y[o,b,f] = sum_i X[i,b,f]*Wsum[i,o,f] (complex). Lane covers freq pair (2*lane, 2*lane+1).
// block: 16b x 8o x 64f; 8 warps; thread 4b x 4o; i chunked by 2, ping-pong cp.async.
// smem (floats): Xs4 f4[2buf][2ii][16b][32q] @0 (32KB) | W2s f2[2][2][8][64] @8192 (16KB)
//                W1s @12288 | W0s @16384 | Wsp f4[2ii][8o][32] @20480 (8KB) ; 88KB total.
__global__ __launch_bounds__(256, 2) void spec_gemm_kernel(const float* __restrict__ w0,
                                                           const float* __restrict__ w1,
                                                           const float* __restrict__ w2, int l){
    extern __shared__ float sm[];
    float4* Xs4 = (float4*)sm;
    float2* W2s = (float2*)(sm + 8192);
    float2* W1s = (float2*)(sm + 12288);
    float2* W0s = (float2*)(sm + 16384);
    float4* Wsp = (float4*)(sm + 20480);
    unsigned sb = (unsigned)__cvta_generic_to_shared(sm);

    int o0 = blockIdx.x * 8;
    int f0 = blockIdx.y * 64;
    int bh = blockIdx.z * 16;
    int tid  = threadIdx.x;
    int lane = tid & 31;
    int g    = tid >> 5;          // 8 warps
    int b0   = (g & 3) * 4;
    int oo   = (g >> 2) * 4;
    bool p1 = (f0 < 1024), p0 = (f0 < 512);
    const float2* W2p = (const float2*)w2 + (size_t)l*HH*HH*2048;
    const float2* W1p = (const float2*)w1 + (size_t)l*HH*HH*1024;
    const float2* W0p = (const float2*)w0 + (size_t)l*HH*HH*512;

    ull accR[4][4], accI[4][4];
    #pragma unroll
    for (int bi = 0; bi < 4; bi++)
        #pragma unroll
        for (int oi = 0; oi < 4; oi++){ accR[bi][oi] = 0ull; accI[bi][oi] = 0ull; }

    // stage chunk (2 i's) into buffer bufs: X 1024 quads (4/thread), W 512 f4/stream (2/thread)
    #define STAGE(c, bufs) do{                                                          \
        int i0s = (c)*2;                                                                \
        _Pragma("unroll")                                                               \
        for (int r = 0; r < 4; r++){                                                    \
            int idx = tid + 256*r;                                                      \
            int ii = idx >> 9, bbq = (idx >> 5) & 15, qq = idx & 31;                    \
            const float4* xsrc = g_X4 + ((size_t)(i0s+ii)*BB + bh + bbq)*1024           \
                                 + (f0 >> 1) + qq;                                      \
            unsigned xslot = ((((bufs)*2 + ii)*16 + bbq)*32 + qq)*16u;                  \
            cpasync16(sb + xslot, xsrc);                                                \
        }                                                                               \
        _Pragma("unroll")                                                               \
        for (int r = 0; r < 2; r++){                                                    \
            int idx = tid + 256*r;                                                      \
            int wii = idx >> 8, wo = (idx >> 5) & 7, wq = (idx & 31) * 2;               \
            size_t wb = ((size_t)(i0s+wii)*HH + o0 + wo);                               \
            unsigned wslot = ((((bufs)*2 + wii)*8 + wo)*64 + wq)*8u;                    \
            cpasync16(sb + 32768u + wslot, W2p + wb*2048 + f0 + wq);                    \
            if (p1) cpasync16(sb + 49152u + wslot, W1p + wb*1024 + f0 + wq);            \
            if (p0) cpasync16(sb + 65536u + wslot, W0p + wb*512  + f0 + wq);            \
        }                                                                               \
    } while(0)

    STAGE(0, 0);
    CP_COMMIT();

    for (int c = 0; c < 32; c++){
        int buf = c & 1;
        CP_WAIT0();
        __syncthreads();
        if (c < 31){ STAGE(c+1, buf^1); CP_COMMIT(); }
        // sum W streams -> Wsp quads (R0,R1,I0,I1); 512 quads over 256 thr
        #pragma unroll
        for (int r = 0; r < 2; r++){
            int idx = tid + 256*r;
            int ii = idx >> 8, o = (idx >> 5) & 7, lp = idx & 31;
            int ws = ((buf*2 + ii)*8 + o)*64 + 2*lp;     // float2 index, 16B aligned
            float4 w = *(const float4*)&W2s[ws];          // (R0,I0,R1,I1)
            if (p1){ float4 a = *(const float4*)&W1s[ws];
                     w.x += a.x; w.y += a.y; w.z += a.z; w.w += a.w; }
            if (p0){ float4 a = *(const float4*)&W0s[ws];
                     w.x += a.x; w.y += a.y; w.z += a.z; w.w += a.w; }
            Wsp[(ii*8 + o)*32 + lp] = make_float4(w.x, w.z, w.y, w.w);  // (R0,R1,I0,I1)
        }
        __syncthreads();
        // consume: per thread 4b x 4o; one LDS.128 per W row / per X row
        #pragma unroll
        for (int ii = 0; ii < 2; ii++){
            ull wr[4], wi[4];
            #pragma unroll
            for (int oi = 0; oi < 4; oi++){
                float4 w = Wsp[((ii*8) + oo + oi)*32 + lane];
                wr[oi] = pack2(w.x, w.y);
                wi[oi] = pack2(w.z, w.w);
            }
            #pragma unroll
            for (int bi = 0; bi < 4; bi++){
                float4 xq = Xs4[((buf*2 + ii)*16 + b0 + bi)*32 + lane];
                ull xr  = pack2(xq.x, xq.y);
                ull xi  = pack2(xq.z, xq.w);
                ull xin = xi ^ 0x8000000080000000ULL;
                #pragma unroll
                for (int oi = 0; oi < 4; oi++){
                    fma2(accR[bi][oi], xr,  wr[oi]);
                    fma2(accR[bi][oi], xin, wi[oi]);
                    fma2(accI[bi][oi], xr,  wi[oi]);
                    fma2(accI[bi][oi], xi,  wr[oi]);
                }
            }
        }
    }
    #undef STAGE

    #pragma unroll
    for (int bi = 0; bi < 4; bi++)
        #pragma unroll
        for (int oi = 0; oi < 4; oi++){
            float2 R = unpack2(accR[bi][oi]);
            float2 I = unpack2(accI[bi][oi]);
            g_Y4[((size_t)(o0 + oo + oi)*BB + bh + b0 + bi)*1024 + (f0 >> 1) + lane]
                = make_float4(R.x, R.y, I.x, I.y);
        }
}

// ---- pointwise: v += conv2(gelu(conv1(s))); register-tiled 4o x 8t ----
__global__ __launch_bounds__(256) void pointwise_kernel(const float* __restrict__ w1,
                                                        const float* __restrict__ b1,
                                                        const float* __restrict__ w2,
                                                        const float* __restrict__ b2, int l){
    int b  = blockIdx.y;
    int t0 = blockIdx.x * 128;
    __shared__ float ss[64][128];
    __shared__ float Wb[64][64];
    int tid = threadIdx.x;
    int ts  = tid & 15;
    int og  = tid >> 4;

    #pragma unroll
    for (int r = 0; r < 16; r++){
        int idx = tid + 256*r;
        int i = idx >> 6, c2 = idx & 63;
        *(float2*)&ss[i][c2*2] = *(const float2*)&g_s[((size_t)b*HH + i)*LL + t0 + c2*2];
    }
    #pragma unroll
    for (int r = 0; r < 16; r++){
        int idx = tid + 256*r;
        Wb[idx >> 6][idx & 63] = w1[(size_t)l*4096 + idx];
    }
    __syncthreads();

    ull acc[4][4];
    #pragma unroll
    for (int oi = 0; oi < 4; oi++){
        float bv = b1[l*HH + og*4 + oi];
        #pragma unroll
        for (int j = 0; j < 4; j++) acc[oi][j] = pack2(bv, bv);
    }
    for (int i = 0; i < 64; i++){
        ull sv[4];
        #pragma unroll
        for (int j = 0; j < 4; j++) sv[j] = *(const ull*)&ss[i][2*ts + 32*j];
        #pragma unroll
        for (int oi = 0; oi < 4; oi++){
            float w = Wb[og*4 + oi][i];
            ull wp = pack2(w, w);
            #pragma unroll
            for (int j = 0; j < 4; j++) fma2(acc[oi][j], wp, sv[j]);
        }
    }
    __syncthreads();
    #pragma unroll
    for (int oi = 0; oi < 4; oi++)
        #pragma unroll
        for (int j = 0; j < 4; j++){
            float2 a = unpack2(acc[oi][j]);
            ss[og*4 + oi][2*ts + 32*j]     = gelu_tanh(a.x);
            ss[og*4 + oi][2*ts + 32*j + 1] = gelu_tanh(a.y);
        }
    #pragma unroll
    for (int r = 0; r < 16; r++){
        int idx = tid + 256*r;
        Wb[idx >> 6][idx & 63] = w2[(size_t)l*4096 + idx];
    }
    __syncthreads();

    ull acc2[4][4];
    #pragma unroll
    for (int ci = 0; ci < 4; ci++){
        float bv = b2[l*HH + og*4 + ci];
        #pragma unroll
        for (int j = 0; j < 4; j++) acc2[ci][j] = pack2(bv, bv);
    }
    for (int o = 0; o < 64; o++){
        ull hv[4];
        #pragma unroll
        for (int j = 0; j < 4; j++) hv[j] = *(const ull*)&ss[o][2*ts + 32*j];
        #pragma unroll
        for (int ci = 0; ci < 4; ci++){
            float w = Wb[og*4 + ci][o];
            ull wp = pack2(w, w);
            #pragma unroll
            for (int j = 0; j < 4; j++) fma2(acc2[ci][j], wp, hv[j]);
        }
    }
    #pragma unroll
    for (int ci = 0; ci < 4; ci++){
        int c = og*4 + ci;
        #pragma unroll
        for (int j = 0; j < 4; j++){
            float2 a = unpack2(acc2[ci][j]);
            float2* vp = (float2*)(g_v + ((size_t)b*HH + c)*LL + t0 + 2*ts + 32*j);
            float2 vv = *vp;
            vv.x += a.x; vv.y += a.y;
            *vp = vv;
        }
    }
}

// ---- decoder ----
__global__ void decoder_kernel(const float* __restrict__ dw, const float* __restrict__ db,
                               float* __restrict__ out){
    int b = blockIdx.y;
    int t = blockIdx.x*256 + threadIdx.x;
    float acc = db[0];
    #pragma unroll 8
    for (int h = 0; h < HH; h++)
        acc += dw[h] * g_v[((size_t)b*HH + h)*LL + t];
    out[(size_t)b*LL + t] = acc;
}

extern "C" void kernel_launch(void* const* d_in, const int* in_sizes, int n_in,
                              void* d_out, int out_size){
    const float* u     = (const float*)d_in[0];
    const float* x     = (const float*)d_in[1];
    const float* enc_w = (const float*)d_in[2];
    const float* enc_b = (const float*)d_in[3];
    const float* dec_w = (const float*)d_in[4];
    const float* dec_b = (const float*)d_in[5];
    const float* c1w   = (const float*)d_in[6];
    const float* c1b   = (const float*)d_in[7];
    const float* c2w   = (const float*)d_in[8];
    const float* c2b   = (const float*)d_in[9];
    const float* sw0   = (const float*)d_in[10];
    const float* sb0   = (const float*)d_in[11];
    const float* sw1   = (const float*)d_in[12];
    const float* sb1   = (const float*)d_in[13];
    const float* sw2   = (const float*)d_in[14];
    const float* sb2   = (const float*)d_in[15];
    float* out = (float*)d_out;

    const int SMEM_SPEC = 22528 * 4;   // 88KB dynamic
    cudaFuncSetAttribute(spec_gemm_kernel,
                         cudaFuncAttributeMaxDynamicSharedMemorySize, SMEM_SPEC);

    init_tw_kernel<<<8, 256>>>();
    encoder_kernel<<<dim3(LL/256, BB), 256>>>(u, x, enc_w, enc_b);
    for (int l = 0; l < 4; l++){
        fft_fwd_kernel<<<dim3(BB, HH), 256>>>();
        spec_gemm_kernel<<<dim3(HH/8, NF/64, 2), 256, SMEM_SPEC>>>(sw0, sw1, sw2, l);
        fft_inv_kernel<<<dim3(BB, HH), 256>>>(sb0, sb1, sb2, l);
        pointwise_kernel<<<dim3(LL/128, BB), 256>>>(c1w, c1b, c2w, c2b, l);
    }
    decoder_kernel<<<dim3(LL/256, BB), 256>>>(dec_w, dec_b, out);
}

// round 12
// speedup vs baseline: 1.1334x; 1.0084x over previous
#include <cuda_runtime.h>

// MSFNO1d: B=32, L=4096, H=64, NL=4, modes {512,1024,2048}
#define BB 32
#define HH 64
#define LL 4096
#define NF 2048

typedef unsigned long long ull;

// ---- scratch (SoA planes for spectral data) ----
__device__ float  g_v[BB*HH*LL];
__device__ float  g_s[BB*HH*LL];
__device__ float  g_Xr[HH*BB*NF];         // Re rfft(v)  [i][b][f]
__device__ float  g_Xi[HH*BB*NF];         // Im
__device__ float  g_Yr[HH*BB*NF];         // Re mixed    [o][b][f]
__device__ float  g_Yi[HH*BB*NF];         // Im
__device__ float2 g_twF[2048];            // e^{-2pi i k/2048}
__device__ float2 g_tw4096[2048];         // e^{-2pi i k/4096}

// ---- helpers ----
__device__ __forceinline__ float2 cmul(float2 a, float2 b){
    return make_float2(a.x*b.x - a.y*b.y, a.x*b.y + a.y*b.x);
}
__device__ __forceinline__ float2 cadd(float2 a, float2 b){ return make_float2(a.x+b.x, a.y+b.y); }
__device__ __forceinline__ float2 csub(float2 a, float2 b){ return make_float2(a.x-b.x, a.y-b.y); }
__device__ __forceinline__ ull pack2(float lo, float hi){
    ull r; asm("mov.b64 %0,{%1,%2};" : "=l"(r) : "f"(lo), "f"(hi)); return r;
}
__device__ __forceinline__ float2 unpack2(ull v){
    float2 r; asm("mov.b64 {%0,%1},%2;" : "=f"(r.x), "=f"(r.y) : "l"(v)); return r;
}
__device__ __forceinline__ void fma2(ull &acc, ull a, ull b){
    asm("fma.rn.f32x2 %0,%1,%2,%0;" : "+l"(acc) : "l"(a), "l"(b));
}
__device__ __forceinline__ float tanh_fast(float x){
    float y; asm("tanh.approx.f32 %0,%1;" : "=f"(y) : "f"(x)); return y;
}
__device__ __forceinline__ float gelu_tanh(float x){
    float x3 = x*x*x;
    return 0.5f*x*(1.0f + tanh_fast(0.7978845608028654f*(x + 0.044715f*x3)));
}
__device__ __forceinline__ void cpasync16(unsigned dst, const void* src){
    asm volatile("cp.async.cg.shared.global [%0], [%1], 16;" :: "r"(dst), "l"(src));
}
#define CP_COMMIT() asm volatile("cp.async.commit_group;")
#define CP_WAIT0()  asm volatile("cp.async.wait_group 0;")

// ---- twiddle init ----
__global__ void init_tw_kernel(){
    int k = blockIdx.x*256 + threadIdx.x;
    if (k < 2048){
        double s, c; sincospi(-2.0*(double)k/2048.0, &s, &c);
        g_twF[k] = make_float2((float)c, (float)s);
        double s2, c2; sincospi(-2.0*(double)k/4096.0, &s2, &c2);
        g_tw4096[k] = make_float2((float)c2, (float)s2);
    }
}

// ---- encoder ----
__global__ void encoder_kernel(const float* __restrict__ u, const float* __restrict__ x,
                               const float* __restrict__ ew, const float* __restrict__ eb){
    int b = blockIdx.y;
    int t = blockIdx.x*256 + threadIdx.x;
    float xv = x[(size_t)b*LL + t];
    float u0 = u[((size_t)b*3 + 0)*LL + t];
    float u1 = u[((size_t)b*3 + 1)*LL + t];
    float u2 = u[((size_t)b*3 + 2)*LL + t];
    #pragma unroll 4
    for (int h = 0; h < HH; h++){
        float r = eb[h] + ew[h*4+0]*xv + ew[h*4+1]*u0 + ew[h*4+2]*u1 + ew[h*4+3]*u2;
        g_v[((size_t)b*HH + h)*LL + t] = r;
    }
}

// ===================== Stockham radix-8 FFT (N=2048, 256 threads) =====================
template<int MODE> __device__ __forceinline__ int swz(int a){
    if (MODE==1) return a ^ (((a>>3) ^ (a>>6)) & 7);     // gen A
    if (MODE==2) return a ^ (((a>>6) & 7) << 3);         // gen B
    return a;                                            // identity
}

__device__ __forceinline__ void radix8(const float2* x, float2* c){
    const float r = 0.70710678118654752f;
    float2 y0 = cadd(x[0],x[4]), y4 = csub(x[0],x[4]);
    float2 y1 = cadd(x[1],x[5]), t5 = csub(x[1],x[5]);
    float2 y2 = cadd(x[2],x[6]), t6 = csub(x[2],x[6]);
    float2 y3 = cadd(x[3],x[7]), t7 = csub(x[3],x[7]);
    float2 y5 = make_float2(r*(t5.x+t5.y), r*(t5.y-t5.x));
    float2 y6 = make_float2(t6.y, -t6.x);
    float2 y7 = make_float2(r*(t7.y-t7.x), -r*(t7.x+t7.y));
    float2 z0 = cadd(y0,y2), z2 = csub(y0,y2);
    float2 z1 = cadd(y1,y3), t3 = csub(y1,y3);
    float2 z3 = make_float2(t3.y, -t3.x);
    float2 z4 = cadd(y4,y6), z6 = csub(y4,y6);
    float2 z5 = cadd(y5,y7), u7 = csub(y5,y7);
    float2 z7 = make_float2(u7.y, -u7.x);
    c[0] = cadd(z0,z1); c[4] = csub(z0,z1);
    c[2] = cadd(z2,z3); c[6] = csub(z2,z3);
    c[1] = cadd(z4,z5); c[5] = csub(z4,z5);
    c[3] = cadd(z6,z7); c[7] = csub(z6,z7);
}

// log-depth twiddle application: c[k] *= w1^k
__device__ __forceinline__ void twchain(float2* c, float2 w1){
    float2 w2 = cmul(w1, w1);
    float2 w3 = cmul(w2, w1);
    float2 w4 = cmul(w2, w2);
    float2 w5 = cmul(w2, w3);
    float2 w6 = cmul(w3, w3);
    float2 w7 = cmul(w3, w4);
    c[1] = cmul(c[1], w1);
    c[2] = cmul(c[2], w2);
    c[3] = cmul(c[3], w3);
    c[4] = cmul(c[4], w4);
    c[5] = cmul(c[5], w5);
    c[6] = cmul(c[6], w6);
    c[7] = cmul(c[7], w7);
}

template<int LOGS, int TSTR, int SWIN, int SWOUT>
__device__ __forceinline__ void stage8s(const float* ri, const float* im,
                                        float* ro, float* io, int tid){
    int q = tid & ((1<<LOGS)-1);
    int p = tid >> LOGS;
    int base = q + (p << LOGS);
    float2 a[8], c[8];
    #pragma unroll
    for (int j = 0; j < 8; j++){
        int s = swz<SWIN>(base + 256*j);
        a[j] = make_float2(ri[s], im[s]);
    }
    radix8(a, c);
    twchain(c, g_twF[p*TSTR]);
    #pragma unroll
    for (int k = 0; k < 8; k++){
        int s = swz<SWOUT>(q + ((8*p + k) << LOGS));
        ro[s] = c[k].x; io[s] = c[k].y;
    }
}

__device__ __forceinline__ void stage8g(const float2* __restrict__ src,
                                        float* ro, float* io, int tid){
    float2 a[8], c[8];
    #pragma unroll
    for (int j = 0; j < 8; j++) a[j] = src[tid + 256*j];
    radix8(a, c);
    twchain(c, g_twF[tid]);
    #pragma unroll
    for (int k = 0; k < 8; k++){
        int s = swz<1>(8*tid + k);
        ro[s] = c[k].x; io[s] = c[k].y;
    }
}

__device__ __forceinline__ void stage4s(const float* ri, const float* im,
                                        float* ro, float* io, int tid){
    #pragma unroll
    for (int h = 0; h < 2; h++){
        int q = tid + 256*h;
        float2 x0 = make_float2(ri[q],      im[q]);
        float2 x1 = make_float2(ri[q+512],  im[q+512]);
        float2 x2 = make_float2(ri[q+1024], im[q+1024]);
        float2 x3 = make_float2(ri[q+1536], im[q+1536]);
        float2 y0 = cadd(x0,x2), y2 = csub(x0,x2);
        float2 y1 = cadd(x1,x3), t3 = csub(x1,x3);
        float2 y3 = make_float2(t3.y, -t3.x);
        float2 c0 = cadd(y0,y1), c2 = csub(y0,y1);
        float2 c1 = cadd(y2,y3), c3 = csub(y2,y3);
        ro[q]      = c0.x; io[q]      = c0.y;
        ro[q+512]  = c1.x; io[q+512]  = c1.y;
        ro[q+1024] = c2.x; io[q+1024] = c2.y;
        ro[q+1536] = c3.x; io[q+1536] = c3.y;
    }
}

// ---- forward rfft: v row (4096 real) -> SoA planes g_Xr/g_Xi ----
__global__ __launch_bounds__(256) void fft_fwd_kernel(){
    __shared__ float r0[2048], i0[2048], r1[2048], i1[2048];
    int b = blockIdx.x, ch = blockIdx.y;
    int tid = threadIdx.x;
    const float2* src = (const float2*)(g_v + ((size_t)b*HH + ch)*LL);
    stage8g(src, r0, i0, tid);
    __syncthreads();
    stage8s<3,8,1,2>(r0, i0, r1, i1, tid);
    __syncthreads();
    stage8s<6,64,2,0>(r1, i1, r0, i0, tid);
    __syncthreads();
    stage4s(r0, i0, r1, i1, tid);
    __syncthreads();
    float* dR = g_Xr + ((size_t)ch*BB + b)*NF;
    float* dI = g_Xi + ((size_t)ch*BB + b)*NF;
    for (int k = tid; k < 2048; k += 256){
        float2 Zk = make_float2(r1[k], i1[k]);
        int kn = (2048 - k) & 2047;
        float2 Zn = make_float2(r1[kn], i1[kn]);
        float2 Fe = make_float2(0.5f*(Zk.x + Zn.x),  0.5f*(Zk.y - Zn.y));
        float2 Fo = make_float2(0.5f*(Zk.y + Zn.y), -0.5f*(Zk.x - Zn.x));
        float2 t  = cmul(g_tw4096[k], Fo);
        dR[k] = Fe.x + t.x;
        dI[k] = Fe.y + t.y;
    }
}

// ---- inverse rfft from SoA planes g_Yr/g_Yi + bias -> g_s ----
__global__ __launch_bounds__(256) void fft_inv_kernel(const float* __restrict__ sb0,
                                                      const float* __restrict__ sb1,
                                                      const float* __restrict__ sb2, int l){
    __shared__ float r0[2048], i0[2048], r1[2048], i1[2048];
    int b = blockIdx.x, o = blockIdx.y;
    int tid = threadIdx.x;
    const float* sR = g_Yr + ((size_t)o*BB + b)*NF;
    const float* sI = g_Yi + ((size_t)o*BB + b)*NF;
    for (int k = tid; k < 2048; k += 256){
        float2 Xk = make_float2(sR[k], sI[k]);
        float2 Xn;
        if (k == 0){ Xk.y = 0.0f; Xn = make_float2(0.0f, 0.0f); }
        else        { Xn = make_float2(sR[2048 - k], sI[2048 - k]); }
        float2 Fe = make_float2(0.5f*(Xk.x + Xn.x), 0.5f*(Xk.y - Xn.y));
        float2 D  = make_float2(0.5f*(Xk.x - Xn.x), 0.5f*(Xk.y + Xn.y));
        float2 w  = g_tw4096[k];
        float2 Fo = make_float2(D.x*w.x + D.y*w.y, D.y*w.x - D.x*w.y);
        r0[k] =  Fe.x - Fo.y;
        i0[k] = -(Fe.y + Fo.x);
    }
    __syncthreads();
    stage8s<0,1,0,1>(r0, i0, r1, i1, tid);
    __syncthreads();
    stage8s<3,8,1,2>(r1, i1, r0, i0, tid);
    __syncthreads();
    stage8s<6,64,2,0>(r0, i0, r1, i1, tid);
    __syncthreads();
    stage4s(r1, i1, r0, i0, tid);
    __syncthreads();
    float bias = sb0[l*HH + o] + sb1[l*HH + o] + sb2[l*HH + o];
    float2* dst = (float2*)(g_s + ((size_t)b*HH + o)*LL);
    const float sc = 1.0f/2048.0f;
    for (int n = tid; n < 2048; n += 256){
        dst[n] = make_float2(r0[n]*sc + bias, -i0[n]*sc + bias);
    }
}

// ===================== spectral mixing v9: R9 pipeline, b-half fastest in grid =========
// Y[o,b,f] = sum_i X[i,b,f]*Wsum[i,o,f] (complex). Lane f32x2 = freqs (f, f+1).
// block: 16b x 8o x 64f; 8 warps; thread 4b x 4o; i chunked by 2, ping-pong cp.async.
// grid: (bh, o, f) with bh FASTEST so the twin blocks sharing a W tile are launch-
// adjacent -> second W read hits L2 (halves W DRAM traffic).
__global__ __launch_bounds__(256, 2) void spec_gemm_kernel(const float* __restrict__ w0,
                                                           const float* __restrict__ w1,
                                                           const float* __restrict__ w2, int l){
    extern __shared__ float sm[];
    float*  XsR = sm;                    // [2buf][2ii][16b][64f]
    float*  XsI = sm + 4096;
    float2* W2s = (float2*)(sm + 8192);  // [2buf][2ii][8o][64f]
    float2* W1s = (float2*)(sm + 12288);
    float2* W0s = (float2*)(sm + 16384);
    float*  WsR = sm + 20480;            // [2ii][8o][64f]
    float*  WsI = sm + 21504;
    unsigned sb = (unsigned)__cvta_generic_to_shared(sm);

    int bh = blockIdx.x * 16;            // FASTEST: twin W-sharing blocks adjacent
    int o0 = blockIdx.y * 8;
    int f0 = blockIdx.z * 64;
    int tid  = threadIdx.x;
    int lane = tid & 31;
    int g    = tid >> 5;          // 8 warps
    int b0   = (g & 3) * 4;
    int oo   = (g >> 2) * 4;
    bool p1 = (f0 < 1024), p0 = (f0 < 512);
    const float2* W2p = (const float2*)w2 + (size_t)l*HH*HH*2048;
    const float2* W1p = (const float2*)w1 + (size_t)l*HH*HH*1024;
    const float2* W0p = (const float2*)w0 + (size_t)l*HH*HH*512;

    ull accR[4][4], accI[4][4];
    #pragma unroll
    for (int bi = 0; bi < 4; bi++)
        #pragma unroll
        for (int oi = 0; oi < 4; oi++){ accR[bi][oi] = 0ull; accI[bi][oi] = 0ull; }

    #define STAGE(c, bufs) do{                                                          \
        int i0s = (c)*2;                                                                \
        _Pragma("unroll")                                                               \
        for (int r = 0; r < 2; r++){                                                    \
            int idx = tid + 256*r;                                                      \
            int ii = idx >> 8, bbq = (idx >> 4) & 15, fq = (idx & 15) * 4;              \
            size_t xofs = ((size_t)(i0s+ii)*BB + bh + bbq)*NF + f0 + fq;                \
            unsigned xslot = ((((bufs)*2 + ii)*16 + bbq)*64 + fq)*4u;                   \
            cpasync16(sb + xslot,          g_Xr + xofs);                                \
            cpasync16(sb + 16384u + xslot, g_Xi + xofs);                                \
            int wii = idx >> 8, wo = (idx >> 5) & 7, wq = (idx & 31) * 2;               \
            size_t wb = ((size_t)(i0s+wii)*HH + o0 + wo);                               \
            unsigned wslot = ((((bufs)*2 + wii)*8 + wo)*64 + wq)*8u;                    \
            cpasync16(sb + 32768u + wslot, W2p + wb*2048 + f0 + wq);                    \
            if (p1) cpasync16(sb + 49152u + wslot, W1p + wb*1024 + f0 + wq);            \
            if (p0) cpasync16(sb + 65536u + wslot, W0p + wb*512  + f0 + wq);            \
        }                                                                               \
    } while(0)

    STAGE(0, 0);
    CP_COMMIT();

    for (int c = 0; c < 32; c++){
        int buf = c & 1;
        CP_WAIT0();
        __syncthreads();
        if (c < 31){ STAGE(c+1, buf^1); CP_COMMIT(); }
        // sum W streams for chunk c -> WsR/WsI (SoA); 1024 complex over 256 thr
        #pragma unroll
        for (int r = 0; r < 4; r++){
            int idx = tid + 256*r;
            int ii = idx >> 9, o = (idx >> 6) & 7, fi = idx & 63;
            int ws = ((buf*2 + ii)*8 + o)*64 + fi;
            float2 wv = W2s[ws];
            if (p1){ float2 a = W1s[ws]; wv.x += a.x; wv.y += a.y; }
            if (p0){ float2 a = W0s[ws]; wv.x += a.x; wv.y += a.y; }
            WsR[(ii*8 + o)*64 + fi] = wv.x;
            WsI[(ii*8 + o)*64 + fi] = wv.y;
        }
        __syncthreads();
        // consume chunk c: per thread 4b x 4o
        #pragma unroll
        for (int ii = 0; ii < 2; ii++){
            ull wr[4], wi[4];
            #pragma unroll
            for (int oi = 0; oi < 4; oi++){
                wr[oi] = *(const ull*)&WsR[((ii*8) + oo + oi)*64 + 2*lane];
                wi[oi] = *(const ull*)&WsI[((ii*8) + oo + oi)*64 + 2*lane];
            }
            #pragma unroll
            for (int bi = 0; bi < 4; bi++){
                int xs = ((buf*2 + ii)*16 + b0 + bi)*64 + 2*lane;
                ull xr  = *(const ull*)&XsR[xs];
                ull xi  = *(const ull*)&XsI[xs];
                ull xin = xi ^ 0x8000000080000000ULL;
                #pragma unroll
                for (int oi = 0; oi < 4; oi++){
                    fma2(accR[bi][oi], xr,  wr[oi]);
                    fma2(accR[bi][oi], xin, wi[oi]);
                    fma2(accI[bi][oi], xr,  wi[oi]);
                    fma2(accI[bi][oi], xi,  wr[oi]);
                }
            }
        }
    }
    #undef STAGE

    #pragma unroll
    for (int bi = 0; bi < 4; bi++)
        #pragma unroll
        for (int oi = 0; oi < 4; oi++){
            size_t ofs = ((size_t)(o0 + oo + oi)*BB + bh + b0 + bi)*NF + f0 + 2*lane;
            *(ull*)&g_Yr[ofs] = accR[bi][oi];
            *(ull*)&g_Yi[ofs] = accI[bi][oi];
        }
}

// ---- pointwise: v += conv2(gelu(conv1(s))); register-tiled 4o x 8t ----
__global__ __launch_bounds__(256) void pointwise_kernel(const float* __restrict__ w1,
                                                        const float* __restrict__ b1,
                                                        const float* __restrict__ w2,
                                                        const float* __restrict__ b2, int l){
    int b  = blockIdx.y;
    int t0 = blockIdx.x * 128;
    __shared__ float ss[64][128];
    __shared__ float Wb[64][64];
    int tid = threadIdx.x;
    int ts  = tid & 15;
    int og  = tid >> 4;

    #pragma unroll
    for (int r = 0; r < 16; r++){
        int idx = tid + 256*r;
        int i = idx >> 6, c2 = idx & 63;
        *(float2*)&ss[i][c2*2] = *(const float2*)&g_s[((size_t)b*HH + i)*LL + t0 + c2*2];
    }
    #pragma unroll
    for (int r = 0; r < 16; r++){
        int idx = tid + 256*r;
        Wb[idx >> 6][idx & 63] = w1[(size_t)l*4096 + idx];
    }
    __syncthreads();

    ull acc[4][4];
    #pragma unroll
    for (int oi = 0; oi < 4; oi++){
        float bv = b1[l*HH + og*4 + oi];
        #pragma unroll
        for (int j = 0; j < 4; j++) acc[oi][j] = pack2(bv, bv);
    }
    for (int i = 0; i < 64; i++){
        ull sv[4];
        #pragma unroll
        for (int j = 0; j < 4; j++) sv[j] = *(const ull*)&ss[i][2*ts + 32*j];
        #pragma unroll
        for (int oi = 0; oi < 4; oi++){
            float w = Wb[og*4 + oi][i];
            ull wp = pack2(w, w);
            #pragma unroll
            for (int j = 0; j < 4; j++) fma2(acc[oi][j], wp, sv[j]);
        }
    }
    __syncthreads();
    #pragma unroll
    for (int oi = 0; oi < 4; oi++)
        #pragma unroll
        for (int j = 0; j < 4; j++){
            float2 a = unpack2(acc[oi][j]);
            ss[og*4 + oi][2*ts + 32*j]     = gelu_tanh(a.x);
            ss[og*4 + oi][2*ts + 32*j + 1] = gelu_tanh(a.y);
        }
    #pragma unroll
    for (int r = 0; r < 16; r++){
        int idx = tid + 256*r;
        Wb[idx >> 6][idx & 63] = w2[(size_t)l*4096 + idx];
    }
    __syncthreads();

    ull acc2[4][4];
    #pragma unroll
    for (int ci = 0; ci < 4; ci++){
        float bv = b2[l*HH + og*4 + ci];
        #pragma unroll
        for (int j = 0; j < 4; j++) acc2[ci][j] = pack2(bv, bv);
    }
    for (int o = 0; o < 64; o++){
        ull hv[4];
        #pragma unroll
        for (int j = 0; j < 4; j++) hv[j] = *(const ull*)&ss[o][2*ts + 32*j];
        #pragma unroll
        for (int ci = 0; ci < 4; ci++){
            float w = Wb[og*4 + ci][o];
            ull wp = pack2(w, w);
            #pragma unroll
            for (int j = 0; j < 4; j++) fma2(acc2[ci][j], wp, hv[j]);
        }
    }
    #pragma unroll
    for (int ci = 0; ci < 4; ci++){
        int c = og*4 + ci;
        #pragma unroll
        for (int j = 0; j < 4; j++){
            float2 a = unpack2(acc2[ci][j]);
            float2* vp = (float2*)(g_v + ((size_t)b*HH + c)*LL + t0 + 2*ts + 32*j);
            float2 vv = *vp;
            vv.x += a.x; vv.y += a.y;
            *vp = vv;
        }
    }
}

// ---- decoder ----
__global__ void decoder_kernel(const float* __restrict__ dw, const float* __restrict__ db,
                               float* __restrict__ out){
    int b = blockIdx.y;
    int t = blockIdx.x*256 + threadIdx.x;
    float acc = db[0];
    #pragma unroll 8
    for (int h = 0; h < HH; h++)
        acc += dw[h] * g_v[((size_t)b*HH + h)*LL + t];
    out[(size_t)b*LL + t] = acc;
}

extern "C" void kernel_launch(void* const* d_in, const int* in_sizes, int n_in,
                              void* d_out, int out_size){
    const float* u     = (const float*)d_in[0];
    const float* x     = (const float*)d_in[1];
    const float* enc_w = (const float*)d_in[2];
    const float* enc_b = (const float*)d_in[3];
    const float* dec_w = (const float*)d_in[4];
    const float* dec_b = (const float*)d_in[5];
    const float* c1w   = (const float*)d_in[6];
    const float* c1b   = (const float*)d_in[7];
    const float* c2w   = (const float*)d_in[8];
    const float* c2b   = (const float*)d_in[9];
    const float* sw0   = (const float*)d_in[10];
    const float* sb0   = (const float*)d_in[11];
    const float* sw1   = (const float*)d_in[12];
    const float* sb1   = (const float*)d_in[13];
    const float* sw2   = (const float*)d_in[14];
    const float* sb2   = (const float*)d_in[15];
    float* out = (float*)d_out;

    const int SMEM_SPEC = 22528 * 4;   // 88KB dynamic
    cudaFuncSetAttribute(spec_gemm_kernel,
                         cudaFuncAttributeMaxDynamicSharedMemorySize, SMEM_SPEC);

    init_tw_kernel<<<8, 256>>>();
    encoder_kernel<<<dim3(LL/256, BB), 256>>>(u, x, enc_w, enc_b);
    for (int l = 0; l < 4; l++){
        fft_fwd_kernel<<<dim3(BB, HH), 256>>>();
        spec_gemm_kernel<<<dim3(2, HH/8, NF/64), 256, SMEM_SPEC>>>(sw0, sw1, sw2, l);
        fft_inv_kernel<<<dim3(BB, HH), 256>>>(sb0, sb1, sb2, l);
        pointwise_kernel<<<dim3(LL/128, BB), 256>>>(c1w, c1b, c2w, c2b, l);
    }
    decoder_kernel<<<dim3(LL/256, BB), 256>>>(dec_w, dec_b, out);
}

// round 13
// speedup vs baseline: 1.1838x; 1.0445x over previous
#include <cuda_runtime.h>

// MSFNO1d: B=32, L=4096, H=64, NL=4, modes {512,1024,2048}
#define BB 32
#define HH 64
#define LL 4096
#define NF 2048

typedef unsigned long long ull;

// ---- scratch (SoA planes for spectral data) ----
__device__ float  g_v[BB*HH*LL];
__device__ float  g_s[BB*HH*LL];
__device__ float  g_Xr[HH*BB*NF];         // Re rfft(v)  [i][b][f]
__device__ float  g_Xi[HH*BB*NF];         // Im
__device__ float  g_Yr[HH*BB*NF];         // Re mixed    [o][b][f]
__device__ float  g_Yi[HH*BB*NF];         // Im
__device__ float2 g_twF[2048];            // e^{-2pi i k/2048}
__device__ float2 g_tw4096[2048];         // e^{-2pi i k/4096}

// ---- helpers ----
__device__ __forceinline__ float2 cmul(float2 a, float2 b){
    return make_float2(a.x*b.x - a.y*b.y, a.x*b.y + a.y*b.x);
}
__device__ __forceinline__ float2 cadd(float2 a, float2 b){ return make_float2(a.x+b.x, a.y+b.y); }
__device__ __forceinline__ float2 csub(float2 a, float2 b){ return make_float2(a.x-b.x, a.y-b.y); }
__device__ __forceinline__ ull pack2(float lo, float hi){
    ull r; asm("mov.b64 %0,{%1,%2};" : "=l"(r) : "f"(lo), "f"(hi)); return r;
}
__device__ __forceinline__ float2 unpack2(ull v){
    float2 r; asm("mov.b64 {%0,%1},%2;" : "=f"(r.x), "=f"(r.y) : "l"(v)); return r;
}
__device__ __forceinline__ void fma2(ull &acc, ull a, ull b){
    asm("fma.rn.f32x2 %0,%1,%2,%0;" : "+l"(acc) : "l"(a), "l"(b));
}
__device__ __forceinline__ float tanh_fast(float x){
    float y; asm("tanh.approx.f32 %0,%1;" : "=f"(y) : "f"(x)); return y;
}
__device__ __forceinline__ float gelu_tanh(float x){
    float x3 = x*x*x;
    return 0.5f*x*(1.0f + tanh_fast(0.7978845608028654f*(x + 0.044715f*x3)));
}
__device__ __forceinline__ void cpasync16(unsigned dst, const void* src){
    asm volatile("cp.async.cg.shared.global [%0], [%1], 16;" :: "r"(dst), "l"(src));
}
#define CP_COMMIT() asm volatile("cp.async.commit_group;")
#define CP_WAIT0()  asm volatile("cp.async.wait_group 0;")

// ---- twiddle init ----
__global__ void init_tw_kernel(){
    int k = blockIdx.x*256 + threadIdx.x;
    if (k < 2048){
        double s, c; sincospi(-2.0*(double)k/2048.0, &s, &c);
        g_twF[k] = make_float2((float)c, (float)s);
        double s2, c2; sincospi(-2.0*(double)k/4096.0, &s2, &c2);
        g_tw4096[k] = make_float2((float)c2, (float)s2);
    }
}

// ---- encoder ----
__global__ void encoder_kernel(const float* __restrict__ u, const float* __restrict__ x,
                               const float* __restrict__ ew, const float* __restrict__ eb){
    int b = blockIdx.y;
    int t = blockIdx.x*256 + threadIdx.x;
    float xv = x[(size_t)b*LL + t];
    float u0 = u[((size_t)b*3 + 0)*LL + t];
    float u1 = u[((size_t)b*3 + 1)*LL + t];
    float u2 = u[((size_t)b*3 + 2)*LL + t];
    #pragma unroll 4
    for (int h = 0; h < HH; h++){
        float r = eb[h] + ew[h*4+0]*xv + ew[h*4+1]*u0 + ew[h*4+2]*u1 + ew[h*4+3]*u2;
        g_v[((size_t)b*HH + h)*LL + t] = r;
    }
}

// ===================== Stockham radix-8 FFT, float2 smem (N=2048, 256 thr) ==============
// swizzles for 8-byte elements (bank = idx mod 16, per 16-lane phase):
//   MODE1 (gen A): injects idx bits[4:7) into bits[0:3)
//   MODE2 (gen B): injects idx bit 6 into bit 3
template<int MODE> __device__ __forceinline__ int swz(int a){
    if (MODE==1) return a ^ ((a>>4) & 7);
    if (MODE==2) return a ^ (((a>>6) & 1) << 3);
    return a;
}

__device__ __forceinline__ void radix8(const float2* x, float2* c){
    const float r = 0.70710678118654752f;
    float2 y0 = cadd(x[0],x[4]), y4 = csub(x[0],x[4]);
    float2 y1 = cadd(x[1],x[5]), t5 = csub(x[1],x[5]);
    float2 y2 = cadd(x[2],x[6]), t6 = csub(x[2],x[6]);
    float2 y3 = cadd(x[3],x[7]), t7 = csub(x[3],x[7]);
    float2 y5 = make_float2(r*(t5.x+t5.y), r*(t5.y-t5.x));
    float2 y6 = make_float2(t6.y, -t6.x);
    float2 y7 = make_float2(r*(t7.y-t7.x), -r*(t7.x+t7.y));
    float2 z0 = cadd(y0,y2), z2 = csub(y0,y2);
    float2 z1 = cadd(y1,y3), t3 = csub(y1,y3);
    float2 z3 = make_float2(t3.y, -t3.x);
    float2 z4 = cadd(y4,y6), z6 = csub(y4,y6);
    float2 z5 = cadd(y5,y7), u7 = csub(y5,y7);
    float2 z7 = make_float2(u7.y, -u7.x);
    c[0] = cadd(z0,z1); c[4] = csub(z0,z1);
    c[2] = cadd(z2,z3); c[6] = csub(z2,z3);
    c[1] = cadd(z4,z5); c[5] = csub(z4,z5);
    c[3] = cadd(z6,z7); c[7] = csub(z6,z7);
}

// log-depth twiddle application: c[k] *= w1^k
__device__ __forceinline__ void twchain(float2* c, float2 w1){
    float2 w2 = cmul(w1, w1);
    float2 w3 = cmul(w2, w1);
    float2 w4 = cmul(w2, w2);
    float2 w5 = cmul(w2, w3);
    float2 w6 = cmul(w3, w3);
    float2 w7 = cmul(w3, w4);
    c[1] = cmul(c[1], w1);
    c[2] = cmul(c[2], w2);
    c[3] = cmul(c[3], w3);
    c[4] = cmul(c[4], w4);
    c[5] = cmul(c[5], w5);
    c[6] = cmul(c[6], w6);
    c[7] = cmul(c[7], w7);
}

template<int LOGS, int TSTR, int SWIN, int SWOUT>
__device__ __forceinline__ void stage8s(const float2* Si, float2* So, int tid){
    int q = tid & ((1<<LOGS)-1);
    int p = tid >> LOGS;
    int base = q + (p << LOGS);
    float2 a[8], c[8];
    #pragma unroll
    for (int j = 0; j < 8; j++) a[j] = Si[swz<SWIN>(base + 256*j)];
    radix8(a, c);
    twchain(c, g_twF[p*TSTR]);
    #pragma unroll
    for (int k = 0; k < 8; k++) So[swz<SWOUT>(q + ((8*p + k) << LOGS))] = c[k];
}

__device__ __forceinline__ void stage8g(const float2* __restrict__ src,
                                        float2* So, int tid){
    float2 a[8], c[8];
    #pragma unroll
    for (int j = 0; j < 8; j++) a[j] = src[tid + 256*j];
    radix8(a, c);
    twchain(c, g_twF[tid]);
    #pragma unroll
    for (int k = 0; k < 8; k++) So[swz<1>(8*tid + k)] = c[k];
}

__device__ __forceinline__ void stage4s(const float2* Si, float2* So, int tid){
    #pragma unroll
    for (int h = 0; h < 2; h++){
        int q = tid + 256*h;
        float2 x0 = Si[q], x1 = Si[q+512], x2 = Si[q+1024], x3 = Si[q+1536];
        float2 y0 = cadd(x0,x2), y2 = csub(x0,x2);
        float2 y1 = cadd(x1,x3), t3 = csub(x1,x3);
        float2 y3 = make_float2(t3.y, -t3.x);
        So[q]      = cadd(y0,y1);
        So[q+512]  = cadd(y2,y3);
        So[q+1024] = csub(y0,y1);
        So[q+1536] = csub(y2,y3);
    }
}

// ---- forward rfft: v row (4096 real) -> SoA planes g_Xr/g_Xi ----
__global__ __launch_bounds__(256, 3) void fft_fwd_kernel(){
    __shared__ float2 SA[2048], SB[2048];
    int b = blockIdx.x, ch = blockIdx.y;
    int tid = threadIdx.x;
    const float2* src = (const float2*)(g_v + ((size_t)b*HH + ch)*LL);
    stage8g(src, SA, tid);                // gmem -> gen A
    __syncthreads();
    stage8s<3,8,1,2>(SA, SB, tid);        // gen A -> gen B
    __syncthreads();
    stage8s<6,64,2,0>(SB, SA, tid);       // gen B -> natural
    __syncthreads();
    stage4s(SA, SB, tid);                 // natural -> natural
    __syncthreads();
    float* dR = g_Xr + ((size_t)ch*BB + b)*NF;
    float* dI = g_Xi + ((size_t)ch*BB + b)*NF;
    #pragma unroll
    for (int r = 0; r < 8; r++){
        int k = tid + 256*r;
        float2 Zk = SB[k];
        float2 Zn = SB[(2048 - k) & 2047];
        float2 Fe = make_float2(0.5f*(Zk.x + Zn.x),  0.5f*(Zk.y - Zn.y));
        float2 Fo = make_float2(0.5f*(Zk.y + Zn.y), -0.5f*(Zk.x - Zn.x));
        float2 t  = cmul(g_tw4096[k], Fo);
        dR[k] = Fe.x + t.x;
        dI[k] = Fe.y + t.y;
    }
}

// ---- inverse rfft from SoA planes g_Yr/g_Yi + bias -> g_s ----
__global__ __launch_bounds__(256, 3) void fft_inv_kernel(const float* __restrict__ sb0,
                                                         const float* __restrict__ sb1,
                                                         const float* __restrict__ sb2, int l){
    __shared__ float2 SA[2048], SB[2048];
    int b = blockIdx.x, o = blockIdx.y;
    int tid = threadIdx.x;
    const float* sR = g_Yr + ((size_t)o*BB + b)*NF;
    const float* sI = g_Yi + ((size_t)o*BB + b)*NF;
    #pragma unroll
    for (int r = 0; r < 8; r++){
        int k = tid + 256*r;
        float2 Xk = make_float2(sR[k], sI[k]);
        float2 Xn;
        if (k == 0){ Xk.y = 0.0f; Xn = make_float2(0.0f, 0.0f); }
        else        { Xn = make_float2(sR[2048 - k], sI[2048 - k]); }
        float2 Fe = make_float2(0.5f*(Xk.x + Xn.x), 0.5f*(Xk.y - Xn.y));
        float2 D  = make_float2(0.5f*(Xk.x - Xn.x), 0.5f*(Xk.y + Xn.y));
        float2 w  = g_tw4096[k];
        float2 Fo = make_float2(D.x*w.x + D.y*w.y, D.y*w.x - D.x*w.y);
        SA[k] = make_float2(Fe.x - Fo.y, -(Fe.y + Fo.x));   // conj -> fwd FFT = IFFT
    }
    __syncthreads();
    stage8s<0,1,0,1>(SA, SB, tid);        // natural -> gen A
    __syncthreads();
    stage8s<3,8,1,2>(SB, SA, tid);        // gen A -> gen B
    __syncthreads();
    stage8s<6,64,2,0>(SA, SB, tid);       // gen B -> natural
    __syncthreads();
    stage4s(SB, SA, tid);
    __syncthreads();
    float bias = sb0[l*HH + o] + sb1[l*HH + o] + sb2[l*HH + o];
    float2* dst = (float2*)(g_s + ((size_t)b*HH + o)*LL);
    const float sc = 1.0f/2048.0f;
    #pragma unroll
    for (int r = 0; r < 8; r++){
        int n = tid + 256*r;
        float2 R = SA[n];
        dst[n] = make_float2(R.x*sc + bias, -R.y*sc + bias);
    }
}

// ===================== spectral mixing (R12): cp.async pipeline, bh fastest =========
__global__ __launch_bounds__(256, 2) void spec_gemm_kernel(const float* __restrict__ w0,
                                                           const float* __restrict__ w1,
                                                           const float* __restrict__ w2, int l){
    extern __shared__ float sm[];
    float*  XsR = sm;                    // [2buf][2ii][16b][64f]
    float*  XsI = sm + 4096;
    float2* W2s = (float2*)(sm + 8192);  // [2buf][2ii][8o][64f]
    float2* W1s = (float2*)(sm + 12288);
    float2* W0s = (float2*)(sm + 16384);
    float*  WsR = sm + 20480;            // [2ii][8o][64f]
    float*  WsI = sm + 21504;
    unsigned sb = (unsigned)__cvta_generic_to_shared(sm);

    int bh = blockIdx.x * 16;            // FASTEST: twin W-sharing blocks adjacent
    int o0 = blockIdx.y * 8;
    int f0 = blockIdx.z * 64;
    int tid  = threadIdx.x;
    int lane = tid & 31;
    int g    = tid >> 5;
    int b0   = (g & 3) * 4;
    int oo   = (g >> 2) * 4;
    bool p1 = (f0 < 1024), p0 = (f0 < 512);
    const float2* W2p = (const float2*)w2 + (size_t)l*HH*HH*2048;
    const float2* W1p = (const float2*)w1 + (size_t)l*HH*HH*1024;
    const float2* W0p = (const float2*)w0 + (size_t)l*HH*HH*512;

    ull accR[4][4], accI[4][4];
    #pragma unroll
    for (int bi = 0; bi < 4; bi++)
        #pragma unroll
        for (int oi = 0; oi < 4; oi++){ accR[bi][oi] = 0ull; accI[bi][oi] = 0ull; }

    #define STAGE(c, bufs) do{                                                          \
        int i0s = (c)*2;                                                                \
        _Pragma("unroll")                                                               \
        for (int r = 0; r < 2; r++){                                                    \
            int idx = tid + 256*r;                                                      \
            int ii = idx >> 8, bbq = (idx >> 4) & 15, fq = (idx & 15) * 4;              \
            size_t xofs = ((size_t)(i0s+ii)*BB + bh + bbq)*NF + f0 + fq;                \
            unsigned xslot = ((((bufs)*2 + ii)*16 + bbq)*64 + fq)*4u;                   \
            cpasync16(sb + xslot,          g_Xr + xofs);                                \
            cpasync16(sb + 16384u + xslot, g_Xi + xofs);                                \
            int wii = idx >> 8, wo = (idx >> 5) & 7, wq = (idx & 31) * 2;               \
            size_t wb = ((size_t)(i0s+wii)*HH + o0 + wo);                               \
            unsigned wslot = ((((bufs)*2 + wii)*8 + wo)*64 + wq)*8u;                    \
            cpasync16(sb + 32768u + wslot, W2p + wb*2048 + f0 + wq);                    \
            if (p1) cpasync16(sb + 49152u + wslot, W1p + wb*1024 + f0 + wq);            \
            if (p0) cpasync16(sb + 65536u + wslot, W0p + wb*512  + f0 + wq);            \
        }                                                                               \
    } while(0)

    STAGE(0, 0);
    CP_COMMIT();

    for (int c = 0; c < 32; c++){
        int buf = c & 1;
        CP_WAIT0();
        __syncthreads();
        if (c < 31){ STAGE(c+1, buf^1); CP_COMMIT(); }
        #pragma unroll
        for (int r = 0; r < 4; r++){
            int idx = tid + 256*r;
            int ii = idx >> 9, o = (idx >> 6) & 7, fi = idx & 63;
            int ws = ((buf*2 + ii)*8 + o)*64 + fi;
            float2 wv = W2s[ws];
            if (p1){ float2 a = W1s[ws]; wv.x += a.x; wv.y += a.y; }
            if (p0){ float2 a = W0s[ws]; wv.x += a.x; wv.y += a.y; }
            WsR[(ii*8 + o)*64 + fi] = wv.x;
            WsI[(ii*8 + o)*64 + fi] = wv.y;
        }
        __syncthreads();
        #pragma unroll
        for (int ii = 0; ii < 2; ii++){
            ull wr[4], wi[4];
            #pragma unroll
            for (int oi = 0; oi < 4; oi++){
                wr[oi] = *(const ull*)&WsR[((ii*8) + oo + oi)*64 + 2*lane];
                wi[oi] = *(const ull*)&WsI[((ii*8) + oo + oi)*64 + 2*lane];
            }
            #pragma unroll
            for (int bi = 0; bi < 4; bi++){
                int xs = ((buf*2 + ii)*16 + b0 + bi)*64 + 2*lane;
                ull xr  = *(const ull*)&XsR[xs];
                ull xi  = *(const ull*)&XsI[xs];
                ull xin = xi ^ 0x8000000080000000ULL;
                #pragma unroll
                for (int oi = 0; oi < 4; oi++){
                    fma2(accR[bi][oi], xr,  wr[oi]);
                    fma2(accR[bi][oi], xin, wi[oi]);
                    fma2(accI[bi][oi], xr,  wi[oi]);
                    fma2(accI[bi][oi], xi,  wr[oi]);
                }
            }
        }
    }
    #undef STAGE

    #pragma unroll
    for (int bi = 0; bi < 4; bi++)
        #pragma unroll
        for (int oi = 0; oi < 4; oi++){
            size_t ofs = ((size_t)(o0 + oo + oi)*BB + bh + b0 + bi)*NF + f0 + 2*lane;
            *(ull*)&g_Yr[ofs] = accR[bi][oi];
            *(ull*)&g_Yi[ofs] = accI[bi][oi];
        }
}

// ---- pointwise: v += conv2(gelu(conv1(s))); register-tiled 4o x 8t ----
__global__ __launch_bounds__(256) void pointwise_kernel(const float* __restrict__ w1,
                                                        const float* __restrict__ b1,
                                                        const float* __restrict__ w2,
                                                        const float* __restrict__ b2, int l){
    int b  = blockIdx.y;
    int t0 = blockIdx.x * 128;
    __shared__ float ss[64][128];
    __shared__ float Wb[64][64];
    int tid = threadIdx.x;
    int ts  = tid & 15;
    int og  = tid >> 4;

    #pragma unroll
    for (int r = 0; r < 16; r++){
        int idx = tid + 256*r;
        int i = idx >> 6, c2 = idx & 63;
        *(float2*)&ss[i][c2*2] = *(const float2*)&g_s[((size_t)b*HH + i)*LL + t0 + c2*2];
    }
    #pragma unroll
    for (int r = 0; r < 16; r++){
        int idx = tid + 256*r;
        Wb[idx >> 6][idx & 63] = w1[(size_t)l*4096 + idx];
    }
    __syncthreads();

    ull acc[4][4];
    #pragma unroll
    for (int oi = 0; oi < 4; oi++){
        float bv = b1[l*HH + og*4 + oi];
        #pragma unroll
        for (int j = 0; j < 4; j++) acc[oi][j] = pack2(bv, bv);
    }
    for (int i = 0; i < 64; i++){
        ull sv[4];
        #pragma unroll
        for (int j = 0; j < 4; j++) sv[j] = *(const ull*)&ss[i][2*ts + 32*j];
        #pragma unroll
        for (int oi = 0; oi < 4; oi++){
            float w = Wb[og*4 + oi][i];
            ull wp = pack2(w, w);
            #pragma unroll
            for (int j = 0; j < 4; j++) fma2(acc[oi][j], wp, sv[j]);
        }
    }
    __syncthreads();
    #pragma unroll
    for (int oi = 0; oi < 4; oi++)
        #pragma unroll
        for (int j = 0; j < 4; j++){
            float2 a = unpack2(acc[oi][j]);
            ss[og*4 + oi][2*ts + 32*j]     = gelu_tanh(a.x);
            ss[og*4 + oi][2*ts + 32*j + 1] = gelu_tanh(a.y);
        }
    #pragma unroll
    for (int r = 0; r < 16; r++){
        int idx = tid + 256*r;
        Wb[idx >> 6][idx & 63] = w2[(size_t)l*4096 + idx];
    }
    __syncthreads();

    ull acc2[4][4];
    #pragma unroll
    for (int ci = 0; ci < 4; ci++){
        float bv = b2[l*HH + og*4 + ci];
        #pragma unroll
        for (int j = 0; j < 4; j++) acc2[ci][j] = pack2(bv, bv);
    }
    for (int o = 0; o < 64; o++){
        ull hv[4];
        #pragma unroll
        for (int j = 0; j < 4; j++) hv[j] = *(const ull*)&ss[o][2*ts + 32*j];
        #pragma unroll
        for (int ci = 0; ci < 4; ci++){
            float w = Wb[og*4 + ci][o];
            ull wp = pack2(w, w);
            #pragma unroll
            for (int j = 0; j < 4; j++) fma2(acc2[ci][j], wp, hv[j]);
        }
    }
    #pragma unroll
    for (int ci = 0; ci < 4; ci++){
        int c = og*4 + ci;
        #pragma unroll
        for (int j = 0; j < 4; j++){
            float2 a = unpack2(acc2[ci][j]);
            float2* vp = (float2*)(g_v + ((size_t)b*HH + c)*LL + t0 + 2*ts + 32*j);
            float2 vv = *vp;
            vv.x += a.x; vv.y += a.y;
            *vp = vv;
        }
    }
}

// ---- decoder ----
__global__ void decoder_kernel(const float* __restrict__ dw, const float* __restrict__ db,
                               float* __restrict__ out){
    int b = blockIdx.y;
    int t = blockIdx.x*256 + threadIdx.x;
    float acc = db[0];
    #pragma unroll 8
    for (int h = 0; h < HH; h++)
        acc += dw[h] * g_v[((size_t)b*HH + h)*LL + t];
    out[(size_t)b*LL + t] = acc;
}

extern "C" void kernel_launch(void* const* d_in, const int* in_sizes, int n_in,
                              void* d_out, int out_size){
    const float* u     = (const float*)d_in[0];
    const float* x     = (const float*)d_in[1];
    const float* enc_w = (const float*)d_in[2];
    const float* enc_b = (const float*)d_in[3];
    const float* dec_w = (const float*)d_in[4];
    const float* dec_b = (const float*)d_in[5];
    const float* c1w   = (const float*)d_in[6];
    const float* c1b   = (const float*)d_in[7];
    const float* c2w   = (const float*)d_in[8];
    const float* c2b   = (const float*)d_in[9];
    const float* sw0   = (const float*)d_in[10];
    const float* sb0   = (const float*)d_in[11];
    const float* sw1   = (const float*)d_in[12];
    const float* sb1   = (const float*)d_in[13];
    const float* sw2   = (const float*)d_in[14];
    const float* sb2   = (const float*)d_in[15];
    float* out = (float*)d_out;

    const int SMEM_SPEC = 22528 * 4;   // 88KB dynamic
    cudaFuncSetAttribute(spec_gemm_kernel,
                         cudaFuncAttributeMaxDynamicSharedMemorySize, SMEM_SPEC);

    init_tw_kernel<<<8, 256>>>();
    encoder_kernel<<<dim3(LL/256, BB), 256>>>(u, x, enc_w, enc_b);
    for (int l = 0; l < 4; l++){
        fft_fwd_kernel<<<dim3(BB, HH), 256>>>();
        spec_gemm_kernel<<<dim3(2, HH/8, NF/64), 256, SMEM_SPEC>>>(sw0, sw1, sw2, l);
        fft_inv_kernel<<<dim3(BB, HH), 256>>>(sb0, sb1, sb2, l);
        pointwise_kernel<<<dim3(LL/128, BB), 256>>>(c1w, c1b, c2w, c2b, l);
    }
    decoder_kernel<<<dim3(LL/256, BB), 256>>>(dec_w, dec_b, out);
}

// round 14
// speedup vs baseline: 1.1908x; 1.0059x over previous
#include <cuda_runtime.h>

// MSFNO1d: B=32, L=4096, H=64, NL=4, modes {512,1024,2048}
#define BB 32
#define HH 64
#define LL 4096
#define NF 2048

typedef unsigned long long ull;

// ---- scratch (SoA planes for spectral data) ----
__device__ float  g_v[BB*HH*LL];
__device__ float  g_s[BB*HH*LL];
__device__ float  g_Xr[HH*BB*NF];         // Re rfft(v)  [i][b][f]
__device__ float  g_Xi[HH*BB*NF];         // Im
__device__ float  g_Yr[HH*BB*NF];         // Re mixed    [o][b][f]
__device__ float  g_Yi[HH*BB*NF];         // Im
__device__ float2 g_twF[2048];            // e^{-2pi i k/2048}
__device__ float2 g_tw4096[2048];         // e^{-2pi i k/4096}

// ---- helpers ----
__device__ __forceinline__ ull pack2(float lo, float hi){
    ull r; asm("mov.b64 %0,{%1,%2};" : "=l"(r) : "f"(lo), "f"(hi)); return r;
}
__device__ __forceinline__ float2 unpack2(ull v){
    float2 r; asm("mov.b64 {%0,%1},%2;" : "=f"(r.x), "=f"(r.y) : "l"(v)); return r;
}
__device__ __forceinline__ void fma2(ull &acc, ull a, ull b){
    asm("fma.rn.f32x2 %0,%1,%2,%0;" : "+l"(acc) : "l"(a), "l"(b));
}
// packed complex add: 1 instruction for both components
__device__ __forceinline__ float2 cadd(float2 a, float2 b){
    ull ua, ub, ur;
    asm("mov.b64 %0,{%1,%2};" : "=l"(ua) : "f"(a.x), "f"(a.y));
    asm("mov.b64 %0,{%1,%2};" : "=l"(ub) : "f"(b.x), "f"(b.y));
    asm("add.rn.f32x2 %0,%1,%2;" : "=l"(ur) : "l"(ua), "l"(ub));
    return unpack2(ur);
}
// packed complex sub: a - b = b*(-1,-1) + a  (one fma.rn.f32x2)
__device__ __forceinline__ float2 csub(float2 a, float2 b){
    const ull NEG1 = 0xBF800000BF800000ULL;
    ull ua, ub, ur;
    asm("mov.b64 %0,{%1,%2};" : "=l"(ua) : "f"(a.x), "f"(a.y));
    asm("mov.b64 %0,{%1,%2};" : "=l"(ub) : "f"(b.x), "f"(b.y));
    asm("fma.rn.f32x2 %0,%1,%2,%3;" : "=l"(ur) : "l"(ub), "l"(NEG1), "l"(ua));
    return unpack2(ur);
}
__device__ __forceinline__ float2 cmul(float2 a, float2 b){
    return make_float2(a.x*b.x - a.y*b.y, a.x*b.y + a.y*b.x);
}
__device__ __forceinline__ float tanh_fast(float x){
    float y; asm("tanh.approx.f32 %0,%1;" : "=f"(y) : "f"(x)); return y;
}
__device__ __forceinline__ float gelu_tanh(float x){
    float x3 = x*x*x;
    return 0.5f*x*(1.0f + tanh_fast(0.7978845608028654f*(x + 0.044715f*x3)));
}
__device__ __forceinline__ void cpasync16(unsigned dst, const void* src){
    asm volatile("cp.async.cg.shared.global [%0], [%1], 16;" :: "r"(dst), "l"(src));
}
#define CP_COMMIT() asm volatile("cp.async.commit_group;")
#define CP_WAIT0()  asm volatile("cp.async.wait_group 0;")

// ---- twiddle init ----
__global__ void init_tw_kernel(){
    int k = blockIdx.x*256 + threadIdx.x;
    if (k < 2048){
        double s, c; sincospi(-2.0*(double)k/2048.0, &s, &c);
        g_twF[k] = make_float2((float)c, (float)s);
        double s2, c2; sincospi(-2.0*(double)k/4096.0, &s2, &c2);
        g_tw4096[k] = make_float2((float)c2, (float)s2);
    }
}

// ---- encoder ----
__global__ void encoder_kernel(const float* __restrict__ u, const float* __restrict__ x,
                               const float* __restrict__ ew, const float* __restrict__ eb){
    int b = blockIdx.y;
    int t = blockIdx.x*256 + threadIdx.x;
    float xv = x[(size_t)b*LL + t];
    float u0 = u[((size_t)b*3 + 0)*LL + t];
    float u1 = u[((size_t)b*3 + 1)*LL + t];
    float u2 = u[((size_t)b*3 + 2)*LL + t];
    #pragma unroll 4
    for (int h = 0; h < HH; h++){
        float r = eb[h] + ew[h*4+0]*xv + ew[h*4+1]*u0 + ew[h*4+2]*u1 + ew[h*4+3]*u2;
        g_v[((size_t)b*HH + h)*LL + t] = r;
    }
}

// ===================== Stockham radix-8 FFT, float2 smem (N=2048, 256 thr) ==============
template<int MODE> __device__ __forceinline__ int swz(int a){
    if (MODE==1) return a ^ ((a>>4) & 7);
    if (MODE==2) return a ^ (((a>>6) & 1) << 3);
    return a;
}

__device__ __forceinline__ void radix8(const float2* x, float2* c){
    const float r = 0.70710678118654752f;
    float2 y0 = cadd(x[0],x[4]), y4 = csub(x[0],x[4]);
    float2 y1 = cadd(x[1],x[5]), t5 = csub(x[1],x[5]);
    float2 y2 = cadd(x[2],x[6]), t6 = csub(x[2],x[6]);
    float2 y3 = cadd(x[3],x[7]), t7 = csub(x[3],x[7]);
    float2 y5 = make_float2(r*(t5.x+t5.y), r*(t5.y-t5.x));
    float2 y6 = make_float2(t6.y, -t6.x);
    float2 y7 = make_float2(r*(t7.y-t7.x), -r*(t7.x+t7.y));
    float2 z0 = cadd(y0,y2), z2 = csub(y0,y2);
    float2 z1 = cadd(y1,y3), t3 = csub(y1,y3);
    float2 z3 = make_float2(t3.y, -t3.x);
    float2 z4 = cadd(y4,y6), z6 = csub(y4,y6);
    float2 z5 = cadd(y5,y7), u7 = csub(y5,y7);
    float2 z7 = make_float2(u7.y, -u7.x);
    c[0] = cadd(z0,z1); c[4] = csub(z0,z1);
    c[2] = cadd(z2,z3); c[6] = csub(z2,z3);
    c[1] = cadd(z4,z5); c[5] = csub(z4,z5);
    c[3] = cadd(z6,z7); c[7] = csub(z6,z7);
}

// log-depth twiddle application: c[k] *= w1^k
__device__ __forceinline__ void twchain(float2* c, float2 w1){
    float2 w2 = cmul(w1, w1);
    float2 w3 = cmul(w2, w1);
    float2 w4 = cmul(w2, w2);
    float2 w5 = cmul(w2, w3);
    float2 w6 = cmul(w3, w3);
    float2 w7 = cmul(w3, w4);
    c[1] = cmul(c[1], w1);
    c[2] = cmul(c[2], w2);
    c[3] = cmul(c[3], w3);
    c[4] = cmul(c[4], w4);
    c[5] = cmul(c[5], w5);
    c[6] = cmul(c[6], w6);
    c[7] = cmul(c[7], w7);
}

template<int LOGS, int TSTR, int SWIN, int SWOUT>
__device__ __forceinline__ void stage8s(const float2* Si, float2* So, int tid){
    int q = tid & ((1<<LOGS)-1);
    int p = tid >> LOGS;
    int base = q + (p << LOGS);
    float2 a[8], c[8];
    #pragma unroll
    for (int j = 0; j < 8; j++) a[j] = Si[swz<SWIN>(base + 256*j)];
    radix8(a, c);
    twchain(c, g_twF[p*TSTR]);
    #pragma unroll
    for (int k = 0; k < 8; k++) So[swz<SWOUT>(q + ((8*p + k) << LOGS))] = c[k];
}

__device__ __forceinline__ void stage8g(const float2* __restrict__ src,
                                        float2* So, int tid){
    float2 a[8], c[8];
    #pragma unroll
    for (int j = 0; j < 8; j++) a[j] = src[tid + 256*j];
    radix8(a, c);
    twchain(c, g_twF[tid]);
    #pragma unroll
    for (int k = 0; k < 8; k++) So[swz<1>(8*tid + k)] = c[k];
}

__device__ __forceinline__ void stage4s(const float2* Si, float2* So, int tid){
    #pragma unroll
    for (int h = 0; h < 2; h++){
        int q = tid + 256*h;
        float2 x0 = Si[q], x1 = Si[q+512], x2 = Si[q+1024], x3 = Si[q+1536];
        float2 y0 = cadd(x0,x2), y2 = csub(x0,x2);
        float2 y1 = cadd(x1,x3), t3 = csub(x1,x3);
        float2 y3 = make_float2(t3.y, -t3.x);
        So[q]      = cadd(y0,y1);
        So[q+512]  = cadd(y2,y3);
        So[q+1024] = csub(y0,y1);
        So[q+1536] = csub(y2,y3);
    }
}

// ---- forward rfft: v row (4096 real) -> SoA planes g_Xr/g_Xi ----
__global__ __launch_bounds__(256, 3) void fft_fwd_kernel(){
    __shared__ float2 SA[2048], SB[2048];
    int b = blockIdx.x, ch = blockIdx.y;
    int tid = threadIdx.x;
    const float2* src = (const float2*)(g_v + ((size_t)b*HH + ch)*LL);
    stage8g(src, SA, tid);                // gmem -> gen A
    __syncthreads();
    stage8s<3,8,1,2>(SA, SB, tid);        // gen A -> gen B
    __syncthreads();
    stage8s<6,64,2,0>(SB, SA, tid);       // gen B -> natural
    __syncthreads();
    stage4s(SA, SB, tid);                 // natural -> natural
    __syncthreads();
    float* dR = g_Xr + ((size_t)ch*BB + b)*NF;
    float* dI = g_Xi + ((size_t)ch*BB + b)*NF;
    #pragma unroll
    for (int r = 0; r < 8; r++){
        int k = tid + 256*r;
        float2 Zk = SB[k];
        float2 Zn = SB[(2048 - k) & 2047];
        float2 Fe = make_float2(0.5f*(Zk.x + Zn.x),  0.5f*(Zk.y - Zn.y));
        float2 Fo = make_float2(0.5f*(Zk.y + Zn.y), -0.5f*(Zk.x - Zn.x));
        float2 t  = cmul(g_tw4096[k], Fo);
        dR[k] = Fe.x + t.x;
        dI[k] = Fe.y + t.y;
    }
}

// ---- inverse rfft from SoA planes g_Yr/g_Yi + bias -> g_s ----
__global__ __launch_bounds__(256, 3) void fft_inv_kernel(const float* __restrict__ sb0,
                                                         const float* __restrict__ sb1,
                                                         const float* __restrict__ sb2, int l){
    __shared__ float2 SA[2048], SB[2048];
    int b = blockIdx.x, o = blockIdx.y;
    int tid = threadIdx.x;
    const float* sR = g_Yr + ((size_t)o*BB + b)*NF;
    const float* sI = g_Yi + ((size_t)o*BB + b)*NF;
    #pragma unroll
    for (int r = 0; r < 8; r++){
        int k = tid + 256*r;
        float2 Xk = make_float2(sR[k], sI[k]);
        float2 Xn;
        if (k == 0){ Xk.y = 0.0f; Xn = make_float2(0.0f, 0.0f); }
        else        { Xn = make_float2(sR[2048 - k], sI[2048 - k]); }
        float2 Fe = make_float2(0.5f*(Xk.x + Xn.x), 0.5f*(Xk.y - Xn.y));
        float2 D  = make_float2(0.5f*(Xk.x - Xn.x), 0.5f*(Xk.y + Xn.y));
        float2 w  = g_tw4096[k];
        float2 Fo = make_float2(D.x*w.x + D.y*w.y, D.y*w.x - D.x*w.y);
        SA[k] = make_float2(Fe.x - Fo.y, -(Fe.y + Fo.x));   // conj -> fwd FFT = IFFT
    }
    __syncthreads();
    stage8s<0,1,0,1>(SA, SB, tid);        // natural -> gen A
    __syncthreads();
    stage8s<3,8,1,2>(SB, SA, tid);        // gen A -> gen B
    __syncthreads();
    stage8s<6,64,2,0>(SA, SB, tid);       // gen B -> natural
    __syncthreads();
    stage4s(SB, SA, tid);
    __syncthreads();
    float bias = sb0[l*HH + o] + sb1[l*HH + o] + sb2[l*HH + o];
    float2* dst = (float2*)(g_s + ((size_t)b*HH + o)*LL);
    const float sc = 1.0f/2048.0f;
    #pragma unroll
    for (int r = 0; r < 8; r++){
        int n = tid + 256*r;
        float2 R = SA[n];
        dst[n] = make_float2(R.x*sc + bias, -R.y*sc + bias);
    }
}

// ===================== spectral mixing (R12): cp.async pipeline, bh fastest =========
__global__ __launch_bounds__(256, 2) void spec_gemm_kernel(const float* __restrict__ w0,
                                                           const float* __restrict__ w1,
                                                           const float* __restrict__ w2, int l){
    extern __shared__ float sm[];
    float*  XsR = sm;                    // [2buf][2ii][16b][64f]
    float*  XsI = sm + 4096;
    float2* W2s = (float2*)(sm + 8192);  // [2buf][2ii][8o][64f]
    float2* W1s = (float2*)(sm + 12288);
    float2* W0s = (float2*)(sm + 16384);
    float*  WsR = sm + 20480;            // [2ii][8o][64f]
    float*  WsI = sm + 21504;
    unsigned sb = (unsigned)__cvta_generic_to_shared(sm);

    int bh = blockIdx.x * 16;            // FASTEST: twin W-sharing blocks adjacent
    int o0 = blockIdx.y * 8;
    int f0 = blockIdx.z * 64;
    int tid  = threadIdx.x;
    int lane = tid & 31;
    int g    = tid >> 5;
    int b0   = (g & 3) * 4;
    int oo   = (g >> 2) * 4;
    bool p1 = (f0 < 1024), p0 = (f0 < 512);
    const float2* W2p = (const float2*)w2 + (size_t)l*HH*HH*2048;
    const float2* W1p = (const float2*)w1 + (size_t)l*HH*HH*1024;
    const float2* W0p = (const float2*)w0 + (size_t)l*HH*HH*512;

    ull accR[4][4], accI[4][4];
    #pragma unroll
    for (int bi = 0; bi < 4; bi++)
        #pragma unroll
        for (int oi = 0; oi < 4; oi++){ accR[bi][oi] = 0ull; accI[bi][oi] = 0ull; }

    #define STAGE(c, bufs) do{                                                          \
        int i0s = (c)*2;                                                                \
        _Pragma("unroll")                                                               \
        for (int r = 0; r < 2; r++){                                                    \
            int idx = tid + 256*r;                                                      \
            int ii = idx >> 8, bbq = (idx >> 4) & 15, fq = (idx & 15) * 4;              \
            size_t xofs = ((size_t)(i0s+ii)*BB + bh + bbq)*NF + f0 + fq;                \
            unsigned xslot = ((((bufs)*2 + ii)*16 + bbq)*64 + fq)*4u;                   \
            cpasync16(sb + xslot,          g_Xr + xofs);                                \
            cpasync16(sb + 16384u + xslot, g_Xi + xofs);                                \
            int wii = idx >> 8, wo = (idx >> 5) & 7, wq = (idx & 31) * 2;               \
            size_t wb = ((size_t)(i0s+wii)*HH + o0 + wo);                               \
            unsigned wslot = ((((bufs)*2 + wii)*8 + wo)*64 + wq)*8u;                    \
            cpasync16(sb + 32768u + wslot, W2p + wb*2048 + f0 + wq);                    \
            if (p1) cpasync16(sb + 49152u + wslot, W1p + wb*1024 + f0 + wq);            \
            if (p0) cpasync16(sb + 65536u + wslot, W0p + wb*512  + f0 + wq);            \
        }                                                                               \
    } while(0)

    STAGE(0, 0);
    CP_COMMIT();

    for (int c = 0; c < 32; c++){
        int buf = c & 1;
        CP_WAIT0();
        __syncthreads();
        if (c < 31){ STAGE(c+1, buf^1); CP_COMMIT(); }
        #pragma unroll
        for (int r = 0; r < 4; r++){
            int idx = tid + 256*r;
            int ii = idx >> 9, o = (idx >> 6) & 7, fi = idx & 63;
            int ws = ((buf*2 + ii)*8 + o)*64 + fi;
            float2 wv = W2s[ws];
            if (p1) wv = cadd(wv, W1s[ws]);
            if (p0) wv = cadd(wv, W0s[ws]);
            WsR[(ii*8 + o)*64 + fi] = wv.x;
            WsI[(ii*8 + o)*64 + fi] = wv.y;
        }
        __syncthreads();
        #pragma unroll
        for (int ii = 0; ii < 2; ii++){
            ull wr[4], wi[4];
            #pragma unroll
            for (int oi = 0; oi < 4; oi++){
                wr[oi] = *(const ull*)&WsR[((ii*8) + oo + oi)*64 + 2*lane];
                wi[oi] = *(const ull*)&WsI[((ii*8) + oo + oi)*64 + 2*lane];
            }
            #pragma unroll
            for (int bi = 0; bi < 4; bi++){
                int xs = ((buf*2 + ii)*16 + b0 + bi)*64 + 2*lane;
                ull xr  = *(const ull*)&XsR[xs];
                ull xi  = *(const ull*)&XsI[xs];
                ull xin = xi ^ 0x8000000080000000ULL;
                #pragma unroll
                for (int oi = 0; oi < 4; oi++){
                    fma2(accR[bi][oi], xr,  wr[oi]);
                    fma2(accR[bi][oi], xin, wi[oi]);
                    fma2(accI[bi][oi], xr,  wi[oi]);
                    fma2(accI[bi][oi], xi,  wr[oi]);
                }
            }
        }
    }
    #undef STAGE

    #pragma unroll
    for (int bi = 0; bi < 4; bi++)
        #pragma unroll
        for (int oi = 0; oi < 4; oi++){
            size_t ofs = ((size_t)(o0 + oo + oi)*BB + bh + b0 + bi)*NF + f0 + 2*lane;
            *(ull*)&g_Yr[ofs] = accR[bi][oi];
            *(ull*)&g_Yi[ofs] = accI[bi][oi];
        }
}

// ---- pointwise: v += conv2(gelu(conv1(s))); register-tiled 4o x 8t ----
__global__ __launch_bounds__(256) void pointwise_kernel(const float* __restrict__ w1,
                                                        const float* __restrict__ b1,
                                                        const float* __restrict__ w2,
                                                        const float* __restrict__ b2, int l){
    int b  = blockIdx.y;
    int t0 = blockIdx.x * 128;
    __shared__ float ss[64][128];
    __shared__ float Wb[64][64];
    int tid = threadIdx.x;
    int ts  = tid & 15;
    int og  = tid >> 4;

    #pragma unroll
    for (int r = 0; r < 16; r++){
        int idx = tid + 256*r;
        int i = idx >> 6, c2 = idx & 63;
        *(float2*)&ss[i][c2*2] = *(const float2*)&g_s[((size_t)b*HH + i)*LL + t0 + c2*2];
    }
    #pragma unroll
    for (int r = 0; r < 16; r++){
        int idx = tid + 256*r;
        Wb[idx >> 6][idx & 63] = w1[(size_t)l*4096 + idx];
    }
    __syncthreads();

    ull acc[4][4];
    #pragma unroll
    for (int oi = 0; oi < 4; oi++){
        float bv = b1[l*HH + og*4 + oi];
        #pragma unroll
        for (int j = 0; j < 4; j++) acc[oi][j] = pack2(bv, bv);
    }
    for (int i = 0; i < 64; i++){
        ull sv[4];
        #pragma unroll
        for (int j = 0; j < 4; j++) sv[j] = *(const ull*)&ss[i][2*ts + 32*j];
        #pragma unroll
        for (int oi = 0; oi < 4; oi++){
            float w = Wb[og*4 + oi][i];
            ull wp = pack2(w, w);
            #pragma unroll
            for (int j = 0; j < 4; j++) fma2(acc[oi][j], wp, sv[j]);
        }
    }
    __syncthreads();
    #pragma unroll
    for (int oi = 0; oi < 4; oi++)
        #pragma unroll
        for (int j = 0; j < 4; j++){
            float2 a = unpack2(acc[oi][j]);
            ss[og*4 + oi][2*ts + 32*j]     = gelu_tanh(a.x);
            ss[og*4 + oi][2*ts + 32*j + 1] = gelu_tanh(a.y);
        }
    #pragma unroll
    for (int r = 0; r < 16; r++){
        int idx = tid + 256*r;
        Wb[idx >> 6][idx & 63] = w2[(size_t)l*4096 + idx];
    }
    __syncthreads();

    ull acc2[4][4];
    #pragma unroll
    for (int ci = 0; ci < 4; ci++){
        float bv = b2[l*HH + og*4 + ci];
        #pragma unroll
        for (int j = 0; j < 4; j++) acc2[ci][j] = pack2(bv, bv);
    }
    for (int o = 0; o < 64; o++){
        ull hv[4];
        #pragma unroll
        for (int j = 0; j < 4; j++) hv[j] = *(const ull*)&ss[o][2*ts + 32*j];
        #pragma unroll
        for (int ci = 0; ci < 4; ci++){
            float w = Wb[og*4 + ci][o];
            ull wp = pack2(w, w);
            #pragma unroll
            for (int j = 0; j < 4; j++) fma2(acc2[ci][j], wp, hv[j]);
        }
    }
    #pragma unroll
    for (int ci = 0; ci < 4; ci++){
        int c = og*4 + ci;
        #pragma unroll
        for (int j = 0; j < 4; j++){
            float2 a = unpack2(acc2[ci][j]);
            float2* vp = (float2*)(g_v + ((size_t)b*HH + c)*LL + t0 + 2*ts + 32*j);
            float2 vv = *vp;
            vv.x += a.x; vv.y += a.y;
            *vp = vv;
        }
    }
}

// ---- decoder ----
__global__ void decoder_kernel(const float* __restrict__ dw, const float* __restrict__ db,
                               float* __restrict__ out){
    int b = blockIdx.y;
    int t = blockIdx.x*256 + threadIdx.x;
    float acc = db[0];
    #pragma unroll 8
    for (int h = 0; h < HH; h++)
        acc += dw[h] * g_v[((size_t)b*HH + h)*LL + t];
    out[(size_t)b*LL + t] = acc;
}

extern "C" void kernel_launch(void* const* d_in, const int* in_sizes, int n_in,
                              void* d_out, int out_size){
    const float* u     = (const float*)d_in[0];
    const float* x     = (const float*)d_in[1];
    const float* enc_w = (const float*)d_in[2];
    const float* enc_b = (const float*)d_in[3];
    const float* dec_w = (const float*)d_in[4];
    const float* dec_b = (const float*)d_in[5];
    const float* c1w   = (const float*)d_in[6];
    const float* c1b   = (const float*)d_in[7];
    const float* c2w   = (const float*)d_in[8];
    const float* c2b   = (const float*)d_in[9];
    const float* sw0   = (const float*)d_in[10];
    const float* sb0   = (const float*)d_in[11];
    const float* sw1   = (const float*)d_in[12];
    const float* sb1   = (const float*)d_in[13];
    const float* sw2   = (const float*)d_in[14];
    const float* sb2   = (const float*)d_in[15];
    float* out = (float*)d_out;

    const int SMEM_SPEC = 22528 * 4;   // 88KB dynamic
    cudaFuncSetAttribute(spec_gemm_kernel,
                         cudaFuncAttributeMaxDynamicSharedMemorySize, SMEM_SPEC);

    init_tw_kernel<<<8, 256>>>();
    encoder_kernel<<<dim3(LL/256, BB), 256>>>(u, x, enc_w, enc_b);
    for (int l = 0; l < 4; l++){
        fft_fwd_kernel<<<dim3(BB, HH), 256>>>();
        spec_gemm_kernel<<<dim3(2, HH/8, NF/64), 256, SMEM_SPEC>>>(sw0, sw1, sw2, l);
        fft_inv_kernel<<<dim3(BB, HH), 256>>>(sb0, sb1, sb2, l);
        pointwise_kernel<<<dim3(LL/128, BB), 256>>>(c1w, c1b, c2w, c2b, l);
    }
    decoder_kernel<<<dim3(LL/256, BB), 256>>>(dec_w, dec_b, out);
}

// round 15
// speedup vs baseline: 1.1972x; 1.0054x over previous
#include <cuda_runtime.h>

// MSFNO1d: B=32, L=4096, H=64, NL=4, modes {512,1024,2048}
#define BB 32
#define HH 64
#define LL 4096
#define NF 2048

typedef unsigned long long ull;

// ---- scratch (SoA planes for spectral data) ----
__device__ float  g_v[BB*HH*LL];
__device__ float  g_s[BB*HH*LL];
__device__ float  g_Xr[HH*BB*NF];         // Re rfft(v)  [i][b][f]
__device__ float  g_Xi[HH*BB*NF];         // Im
__device__ float  g_Yr[HH*BB*NF];         // Re mixed    [o][b][f]
__device__ float  g_Yi[HH*BB*NF];         // Im
__device__ float2 g_twF[2048];            // e^{-2pi i k/2048}
__device__ float2 g_tw4096[2048];         // e^{-2pi i k/4096}

// ---- helpers ----
__device__ __forceinline__ ull pack2(float lo, float hi){
    ull r; asm("mov.b64 %0,{%1,%2};" : "=l"(r) : "f"(lo), "f"(hi)); return r;
}
__device__ __forceinline__ float2 unpack2(ull v){
    float2 r; asm("mov.b64 {%0,%1},%2;" : "=f"(r.x), "=f"(r.y) : "l"(v)); return r;
}
__device__ __forceinline__ void fma2(ull &acc, ull a, ull b){
    asm("fma.rn.f32x2 %0,%1,%2,%0;" : "+l"(acc) : "l"(a), "l"(b));
}
// packed complex add: 1 instruction for both components
__device__ __forceinline__ float2 cadd(float2 a, float2 b){
    ull ua, ub, ur;
    asm("mov.b64 %0,{%1,%2};" : "=l"(ua) : "f"(a.x), "f"(a.y));
    asm("mov.b64 %0,{%1,%2};" : "=l"(ub) : "f"(b.x), "f"(b.y));
    asm("add.rn.f32x2 %0,%1,%2;" : "=l"(ur) : "l"(ua), "l"(ub));
    return unpack2(ur);
}
// packed complex sub: a - b = b*(-1,-1) + a  (one fma.rn.f32x2)
__device__ __forceinline__ float2 csub(float2 a, float2 b){
    const ull NEG1 = 0xBF800000BF800000ULL;
    ull ua, ub, ur;
    asm("mov.b64 %0,{%1,%2};" : "=l"(ua) : "f"(a.x), "f"(a.y));
    asm("mov.b64 %0,{%1,%2};" : "=l"(ub) : "f"(b.x), "f"(b.y));
    asm("fma.rn.f32x2 %0,%1,%2,%3;" : "=l"(ur) : "l"(ub), "l"(NEG1), "l"(ua));
    return unpack2(ur);
}
__device__ __forceinline__ float2 cmul(float2 a, float2 b){
    return make_float2(a.x*b.x - a.y*b.y, a.x*b.y + a.y*b.x);
}
__device__ __forceinline__ float tanh_fast(float x){
    float y; asm("tanh.approx.f32 %0,%1;" : "=f"(y) : "f"(x)); return y;
}
__device__ __forceinline__ float gelu_tanh(float x){
    float x3 = x*x*x;
    return 0.5f*x*(1.0f + tanh_fast(0.7978845608028654f*(x + 0.044715f*x3)));
}
__device__ __forceinline__ void cpasync16(unsigned dst, const void* src){
    asm volatile("cp.async.cg.shared.global [%0], [%1], 16;" :: "r"(dst), "l"(src));
}
#define CP_COMMIT() asm volatile("cp.async.commit_group;")

// ---- twiddle init ----
__global__ void init_tw_kernel(){
    int k = blockIdx.x*256 + threadIdx.x;
    if (k < 2048){
        double s, c; sincospi(-2.0*(double)k/2048.0, &s, &c);
        g_twF[k] = make_float2((float)c, (float)s);
        double s2, c2; sincospi(-2.0*(double)k/4096.0, &s2, &c2);
        g_tw4096[k] = make_float2((float)c2, (float)s2);
    }
}

// ---- encoder ----
__global__ void encoder_kernel(const float* __restrict__ u, const float* __restrict__ x,
                               const float* __restrict__ ew, const float* __restrict__ eb){
    int b = blockIdx.y;
    int t = blockIdx.x*256 + threadIdx.x;
    float xv = x[(size_t)b*LL + t];
    float u0 = u[((size_t)b*3 + 0)*LL + t];
    float u1 = u[((size_t)b*3 + 1)*LL + t];
    float u2 = u[((size_t)b*3 + 2)*LL + t];
    #pragma unroll 4
    for (int h = 0; h < HH; h++){
        float r = eb[h] + ew[h*4+0]*xv + ew[h*4+1]*u0 + ew[h*4+2]*u1 + ew[h*4+3]*u2;
        g_v[((size_t)b*HH + h)*LL + t] = r;
    }
}

// ===================== Stockham radix-8 FFT, float2 smem (N=2048, 256 thr) ==============
template<int MODE> __device__ __forceinline__ int swz(int a){
    if (MODE==1) return a ^ ((a>>4) & 7);
    if (MODE==2) return a ^ (((a>>6) & 1) << 3);
    return a;
}

__device__ __forceinline__ void radix8(const float2* x, float2* c){
    const float r = 0.70710678118654752f;
    float2 y0 = cadd(x[0],x[4]), y4 = csub(x[0],x[4]);
    float2 y1 = cadd(x[1],x[5]), t5 = csub(x[1],x[5]);
    float2 y2 = cadd(x[2],x[6]), t6 = csub(x[2],x[6]);
    float2 y3 = cadd(x[3],x[7]), t7 = csub(x[3],x[7]);
    float2 y5 = make_float2(r*(t5.x+t5.y), r*(t5.y-t5.x));
    float2 y6 = make_float2(t6.y, -t6.x);
    float2 y7 = make_float2(r*(t7.y-t7.x), -r*(t7.x+t7.y));
    float2 z0 = cadd(y0,y2), z2 = csub(y0,y2);
    float2 z1 = cadd(y1,y3), t3 = csub(y1,y3);
    float2 z3 = make_float2(t3.y, -t3.x);
    float2 z4 = cadd(y4,y6), z6 = csub(y4,y6);
    float2 z5 = cadd(y5,y7), u7 = csub(y5,y7);
    float2 z7 = make_float2(u7.y, -u7.x);
    c[0] = cadd(z0,z1); c[4] = csub(z0,z1);
    c[2] = cadd(z2,z3); c[6] = csub(z2,z3);
    c[1] = cadd(z4,z5); c[5] = csub(z4,z5);
    c[3] = cadd(z6,z7); c[7] = csub(z6,z7);
}

// log-depth twiddle application: c[k] *= w1^k
__device__ __forceinline__ void twchain(float2* c, float2 w1){
    float2 w2 = cmul(w1, w1);
    float2 w3 = cmul(w2, w1);
    float2 w4 = cmul(w2, w2);
    float2 w5 = cmul(w2, w3);
    float2 w6 = cmul(w3, w3);
    float2 w7 = cmul(w3, w4);
    c[1] = cmul(c[1], w1);
    c[2] = cmul(c[2], w2);
    c[3] = cmul(c[3], w3);
    c[4] = cmul(c[4], w4);
    c[5] = cmul(c[5], w5);
    c[6] = cmul(c[6], w6);
    c[7] = cmul(c[7], w7);
}

template<int LOGS, int TSTR, int SWIN, int SWOUT>
__device__ __forceinline__ void stage8s(const float2* Si, float2* So, int tid){
    int q = tid & ((1<<LOGS)-1);
    int p = tid >> LOGS;
    int base = q + (p << LOGS);
    float2 a[8], c[8];
    #pragma unroll
    for (int j = 0; j < 8; j++) a[j] = Si[swz<SWIN>(base + 256*j)];
    radix8(a, c);
    twchain(c, g_twF[p*TSTR]);
    #pragma unroll
    for (int k = 0; k < 8; k++) So[swz<SWOUT>(q + ((8*p + k) << LOGS))] = c[k];
}

__device__ __forceinline__ void stage8g(const float2* __restrict__ src,
                                        float2* So, int tid){
    float2 a[8], c[8];
    #pragma unroll
    for (int j = 0; j < 8; j++) a[j] = src[tid + 256*j];
    radix8(a, c);
    twchain(c, g_twF[tid]);
    #pragma unroll
    for (int k = 0; k < 8; k++) So[swz<1>(8*tid + k)] = c[k];
}

__device__ __forceinline__ void stage4s(const float2* Si, float2* So, int tid){
    #pragma unroll
    for (int h = 0; h < 2; h++){
        int q = tid + 256*h;
        float2 x0 = Si[q], x1 = Si[q+512], x2 = Si[q+1024], x3 = Si[q+1536];
        float2 y0 = cadd(x0,x2), y2 = csub(x0,x2);
        float2 y1 = cadd(x1,x3), t3 = csub(x1,x3);
        float2 y3 = make_float2(t3.y, -t3.x);
        So[q]      = cadd(y0,y1);
        So[q+512]  = cadd(y2,y3);
        So[q+1024] = csub(y0,y1);
        So[q+1536] = csub(y2,y3);
    }
}

// ---- forward rfft: v row (4096 real) -> SoA planes g_Xr/g_Xi ----
__global__ __launch_bounds__(256, 4) void fft_fwd_kernel(){
    __shared__ float2 SA[2048], SB[2048];
    int b = blockIdx.x, ch = blockIdx.y;
    int tid = threadIdx.x;
    const float2* src = (const float2*)(g_v + ((size_t)b*HH + ch)*LL);
    stage8g(src, SA, tid);                // gmem -> gen A
    __syncthreads();
    stage8s<3,8,1,2>(SA, SB, tid);        // gen A -> gen B
    __syncthreads();
    stage8s<6,64,2,0>(SB, SA, tid);       // gen B -> natural
    __syncthreads();
    stage4s(SA, SB, tid);                 // natural -> natural
    __syncthreads();
    float* dR = g_Xr + ((size_t)ch*BB + b)*NF;
    float* dI = g_Xi + ((size_t)ch*BB + b)*NF;
    #pragma unroll
    for (int r = 0; r < 8; r++){
        int k = tid + 256*r;
        float2 Zk = SB[k];
        float2 Zn = SB[(2048 - k) & 2047];
        float2 Fe = make_float2(0.5f*(Zk.x + Zn.x),  0.5f*(Zk.y - Zn.y));
        float2 Fo = make_float2(0.5f*(Zk.y + Zn.y), -0.5f*(Zk.x - Zn.x));
        float2 t  = cmul(g_tw4096[k], Fo);
        dR[k] = Fe.x + t.x;
        dI[k] = Fe.y + t.y;
    }
}

// ---- inverse rfft from SoA planes g_Yr/g_Yi + bias -> g_s ----
__global__ __launch_bounds__(256, 4) void fft_inv_kernel(const float* __restrict__ sb0,
                                                         const float* __restrict__ sb1,
                                                         const float* __restrict__ sb2, int l){
    __shared__ float2 SA[2048], SB[2048];
    int b = blockIdx.x, o = blockIdx.y;
    int tid = threadIdx.x;
    const float* sR = g_Yr + ((size_t)o*BB + b)*NF;
    const float* sI = g_Yi + ((size_t)o*BB + b)*NF;
    #pragma unroll
    for (int r = 0; r < 8; r++){
        int k = tid + 256*r;
        float2 Xk = make_float2(sR[k], sI[k]);
        float2 Xn;
        if (k == 0){ Xk.y = 0.0f; Xn = make_float2(0.0f, 0.0f); }
        else        { Xn = make_float2(sR[2048 - k], sI[2048 - k]); }
        float2 Fe = make_float2(0.5f*(Xk.x + Xn.x), 0.5f*(Xk.y - Xn.y));
        float2 D  = make_float2(0.5f*(Xk.x - Xn.x), 0.5f*(Xk.y + Xn.y));
        float2 w  = g_tw4096[k];
        float2 Fo = make_float2(D.x*w.x + D.y*w.y, D.y*w.x - D.x*w.y);
        SA[k] = make_float2(Fe.x - Fo.y, -(Fe.y + Fo.x));   // conj -> fwd FFT = IFFT
    }
    __syncthreads();
    stage8s<0,1,0,1>(SA, SB, tid);        // natural -> gen A
    __syncthreads();
    stage8s<3,8,1,2>(SB, SA, tid);        // gen A -> gen B
    __syncthreads();
    stage8s<6,64,2,0>(SA, SB, tid);       // gen B -> natural
    __syncthreads();
    stage4s(SB, SA, tid);
    __syncthreads();
    float bias = sb0[l*HH + o] + sb1[l*HH + o] + sb2[l*HH + o];
    float2* dst = (float2*)(g_s + ((size_t)b*HH + o)*LL);
    const float sc = 1.0f/2048.0f;
    #pragma unroll
    for (int r = 0; r < 8; r++){
        int n = tid + 256*r;
        float2 R = SA[n];
        dst[n] = make_float2(R.x*sc + bias, -R.y*sc + bias);
    }
}

// ===================== spectral mixing: proper 1-ahead cp.async rotation ==============
__global__ __launch_bounds__(256, 2) void spec_gemm_kernel(const float* __restrict__ w0,
                                                           const float* __restrict__ w1,
                                                           const float* __restrict__ w2, int l){
    extern __shared__ float sm[];
    float*  XsR = sm;                    // [2buf][2ii][16b][64f]
    float*  XsI = sm + 4096;
    float2* W2s = (float2*)(sm + 8192);  // [2buf][2ii][8o][64f]
    float2* W1s = (float2*)(sm + 12288);
    float2* W0s = (float2*)(sm + 16384);
    float*  WsR = sm + 20480;            // [2ii][8o][64f]
    float*  WsI = sm + 21504;
    unsigned sb = (unsigned)__cvta_generic_to_shared(sm);

    int bh = blockIdx.x * 16;            // FASTEST: twin W-sharing blocks adjacent
    int o0 = blockIdx.y * 8;
    int f0 = blockIdx.z * 64;
    int tid  = threadIdx.x;
    int lane = tid & 31;
    int g    = tid >> 5;
    int b0   = (g & 3) * 4;
    int oo   = (g >> 2) * 4;
    bool p1 = (f0 < 1024), p0 = (f0 < 512);
    const float2* W2p = (const float2*)w2 + (size_t)l*HH*HH*2048;
    const float2* W1p = (const float2*)w1 + (size_t)l*HH*HH*1024;
    const float2* W0p = (const float2*)w0 + (size_t)l*HH*HH*512;

    ull accR[4][4], accI[4][4];
    #pragma unroll
    for (int bi = 0; bi < 4; bi++)
        #pragma unroll
        for (int oi = 0; oi < 4; oi++){ accR[bi][oi] = 0ull; accI[bi][oi] = 0ull; }

    #define STAGE(c, bufs) do{                                                          \
        int i0s = (c)*2;                                                                \
        _Pragma("unroll")                                                               \
        for (int r = 0; r < 2; r++){                                                    \
            int idx = tid + 256*r;                                                      \
            int ii = idx >> 8, bbq = (idx >> 4) & 15, fq = (idx & 15) * 4;              \
            size_t xofs = ((size_t)(i0s+ii)*BB + bh + bbq)*NF + f0 + fq;                \
            unsigned xslot = ((((bufs)*2 + ii)*16 + bbq)*64 + fq)*4u;                   \
            cpasync16(sb + xslot,          g_Xr + xofs);                                \
            cpasync16(sb + 16384u + xslot, g_Xi + xofs);                                \
            int wii = idx >> 8, wo = (idx >> 5) & 7, wq = (idx & 31) * 2;               \
            size_t wb = ((size_t)(i0s+wii)*HH + o0 + wo);                               \
            unsigned wslot = ((((bufs)*2 + wii)*8 + wo)*64 + wq)*8u;                    \
            cpasync16(sb + 32768u + wslot, W2p + wb*2048 + f0 + wq);                    \
            if (p1) cpasync16(sb + 49152u + wslot, W1p + wb*1024 + f0 + wq);            \
            if (p0) cpasync16(sb + 65536u + wslot, W0p + wb*512  + f0 + wq);            \
        }                                                                               \
    } while(0)

    STAGE(0, 0);
    CP_COMMIT();

    for (int c = 0; c < 32; c++){
        int buf = c & 1;
        __syncthreads();                 // all threads done reading buf^1 (chunk c-1)
        if (c < 31){
            STAGE(c+1, buf^1);           // stage next chunk; stays IN FLIGHT during compute
            CP_COMMIT();
            asm volatile("cp.async.wait_group 1;");   // chunk c arrived; c+1 still flying
        } else {
            asm volatile("cp.async.wait_group 0;");
        }
        __syncthreads();                 // chunk c visible to all threads
        // sum W streams for chunk c -> WsR/WsI (SoA)
        #pragma unroll
        for (int r = 0; r < 4; r++){
            int idx = tid + 256*r;
            int ii = idx >> 9, o = (idx >> 6) & 7, fi = idx & 63;
            int ws = ((buf*2 + ii)*8 + o)*64 + fi;
            float2 wv = W2s[ws];
            if (p1) wv = cadd(wv, W1s[ws]);
            if (p0) wv = cadd(wv, W0s[ws]);
            WsR[(ii*8 + o)*64 + fi] = wv.x;
            WsI[(ii*8 + o)*64 + fi] = wv.y;
        }
        __syncthreads();
        // consume chunk c: per thread 4b x 4o
        #pragma unroll
        for (int ii = 0; ii < 2; ii++){
            ull wr[4], wi[4];
            #pragma unroll
            for (int oi = 0; oi < 4; oi++){
                wr[oi] = *(const ull*)&WsR[((ii*8) + oo + oi)*64 + 2*lane];
                wi[oi] = *(const ull*)&WsI[((ii*8) + oo + oi)*64 + 2*lane];
            }
            #pragma unroll
            for (int bi = 0; bi < 4; bi++){
                int xs = ((buf*2 + ii)*16 + b0 + bi)*64 + 2*lane;
                ull xr  = *(const ull*)&XsR[xs];
                ull xi  = *(const ull*)&XsI[xs];
                ull xin = xi ^ 0x8000000080000000ULL;
                #pragma unroll
                for (int oi = 0; oi < 4; oi++){
                    fma2(accR[bi][oi], xr,  wr[oi]);
                    fma2(accR[bi][oi], xin, wi[oi]);
                    fma2(accI[bi][oi], xr,  wi[oi]);
                    fma2(accI[bi][oi], xi,  wr[oi]);
                }
            }
        }
    }
    #undef STAGE

    #pragma unroll
    for (int bi = 0; bi < 4; bi++)
        #pragma unroll
        for (int oi = 0; oi < 4; oi++){
            size_t ofs = ((size_t)(o0 + oo + oi)*BB + bh + b0 + bi)*NF + f0 + 2*lane;
            *(ull*)&g_Yr[ofs] = accR[bi][oi];
            *(ull*)&g_Yi[ofs] = accI[bi][oi];
        }
}

// ---- pointwise: v += conv2(gelu(conv1(s))); register-tiled 4o x 8t ----
__global__ __launch_bounds__(256) void pointwise_kernel(const float* __restrict__ w1,
                                                        const float* __restrict__ b1,
                                                        const float* __restrict__ w2,
                                                        const float* __restrict__ b2, int l){
    int b  = blockIdx.y;
    int t0 = blockIdx.x * 128;
    __shared__ float ss[64][128];
    __shared__ float Wb[64][64];
    int tid = threadIdx.x;
    int ts  = tid & 15;
    int og  = tid >> 4;

    #pragma unroll
    for (int r = 0; r < 16; r++){
        int idx = tid + 256*r;
        int i = idx >> 6, c2 = idx & 63;
        *(float2*)&ss[i][c2*2] = *(const float2*)&g_s[((size_t)b*HH + i)*LL + t0 + c2*2];
    }
    #pragma unroll
    for (int r = 0; r < 16; r++){
        int idx = tid + 256*r;
        Wb[idx >> 6][idx & 63] = w1[(size_t)l*4096 + idx];
    }
    __syncthreads();

    ull acc[4][4];
    #pragma unroll
    for (int oi = 0; oi < 4; oi++){
        float bv = b1[l*HH + og*4 + oi];
        #pragma unroll
        for (int j = 0; j < 4; j++) acc[oi][j] = pack2(bv, bv);
    }
    for (int i = 0; i < 64; i++){
        ull sv[4];
        #pragma unroll
        for (int j = 0; j < 4; j++) sv[j] = *(const ull*)&ss[i][2*ts + 32*j];
        #pragma unroll
        for (int oi = 0; oi < 4; oi++){
            float w = Wb[og*4 + oi][i];
            ull wp = pack2(w, w);
            #pragma unroll
            for (int j = 0; j < 4; j++) fma2(acc[oi][j], wp, sv[j]);
        }
    }
    __syncthreads();
    #pragma unroll
    for (int oi = 0; oi < 4; oi++)
        #pragma unroll
        for (int j = 0; j < 4; j++){
            float2 a = unpack2(acc[oi][j]);
            ss[og*4 + oi][2*ts + 32*j]     = gelu_tanh(a.x);
            ss[og*4 + oi][2*ts + 32*j + 1] = gelu_tanh(a.y);
        }
    #pragma unroll
    for (int r = 0; r < 16; r++){
        int idx = tid + 256*r;
        Wb[idx >> 6][idx & 63] = w2[(size_t)l*4096 + idx];
    }
    __syncthreads();

    ull acc2[4][4];
    #pragma unroll
    for (int ci = 0; ci < 4; ci++){
        float bv = b2[l*HH + og*4 + ci];
        #pragma unroll
        for (int j = 0; j < 4; j++) acc2[ci][j] = pack2(bv, bv);
    }
    for (int o = 0; o < 64; o++){
        ull hv[4];
        #pragma unroll
        for (int j = 0; j < 4; j++) hv[j] = *(const ull*)&ss[o][2*ts + 32*j];
        #pragma unroll
        for (int ci = 0; ci < 4; ci++){
            float w = Wb[og*4 + ci][o];
            ull wp = pack2(w, w);
            #pragma unroll
            for (int j = 0; j < 4; j++) fma2(acc2[ci][j], wp, hv[j]);
        }
    }
    #pragma unroll
    for (int ci = 0; ci < 4; ci++){
        int c = og*4 + ci;
        #pragma unroll
        for (int j = 0; j < 4; j++){
            float2 a = unpack2(acc2[ci][j]);
            float2* vp = (float2*)(g_v + ((size_t)b*HH + c)*LL + t0 + 2*ts + 32*j);
            float2 vv = *vp;
            vv.x += a.x; vv.y += a.y;
            *vp = vv;
        }
    }
}

// ---- decoder ----
__global__ void decoder_kernel(const float* __restrict__ dw, const float* __restrict__ db,
                               float* __restrict__ out){
    int b = blockIdx.y;
    int t = blockIdx.x*256 + threadIdx.x;
    float acc = db[0];
    #pragma unroll 8
    for (int h = 0; h < HH; h++)
        acc += dw[h] * g_v[((size_t)b*HH + h)*LL + t];
    out[(size_t)b*LL + t] = acc;
}

extern "C" void kernel_launch(void* const* d_in, const int* in_sizes, int n_in,
                              void* d_out, int out_size){
    const float* u     = (const float*)d_in[0];
    const float* x     = (const float*)d_in[1];
    const float* enc_w = (const float*)d_in[2];
    const float* enc_b = (const float*)d_in[3];
    const float* dec_w = (const float*)d_in[4];
    const float* dec_b = (const float*)d_in[5];
    const float* c1w   = (const float*)d_in[6];
    const float* c1b   = (const float*)d_in[7];
    const float* c2w   = (const float*)d_in[8];
    const float* c2b   = (const float*)d_in[9];
    const float* sw0   = (const float*)d_in[10];
    const float* sb0   = (const float*)d_in[11];
    const float* sw1   = (const float*)d_in[12];
    const float* sb1   = (const float*)d_in[13];
    const float* sw2   = (const float*)d_in[14];
    const float* sb2   = (const float*)d_in[15];
    float* out = (float*)d_out;

    const int SMEM_SPEC = 22528 * 4;   // 88KB dynamic
    cudaFuncSetAttribute(spec_gemm_kernel,
                         cudaFuncAttributeMaxDynamicSharedMemorySize, SMEM_SPEC);

    init_tw_kernel<<<8, 256>>>();
    encoder_kernel<<<dim3(LL/256, BB), 256>>>(u, x, enc_w, enc_b);
    for (int l = 0; l < 4; l++){
        fft_fwd_kernel<<<dim3(BB, HH), 256>>>();
        spec_gemm_kernel<<<dim3(2, HH/8, NF/64), 256, SMEM_SPEC>>>(sw0, sw1, sw2, l);
        fft_inv_kernel<<<dim3(BB, HH), 256>>>(sb0, sb1, sb2, l);
        pointwise_kernel<<<dim3(LL/128, BB), 256>>>(c1w, c1b, c2w, c2b, l);
    }
    decoder_kernel<<<dim3(LL/256, BB), 256>>>(dec_w, dec_b, out);
}